// round 1
// baseline (speedup 1.0000x reference)
#include <cuda_runtime.h>
#include <cuda_bf16.h>
#include <math.h>

// Problem constants
constexpr int BB  = 2;
constexpr int TT  = 2048;
constexpr int CC  = 2048;
constexpr int HH  = 16;
constexpr int HKVV = 4;
constexpr int DD  = 128;
constexpr int RR  = 64;
constexpr int KVC = HKVV * DD;      // 512
constexpr int REP = HH / HKVV;      // 4
constexpr int MROWS = BB * TT;      // 4096

// ---------------------------------------------------------------------------
// Scratch (static __device__ arrays; no allocations allowed)
// ---------------------------------------------------------------------------
__device__ float g_q[(size_t)MROWS * CC];   // 33.5 MB
__device__ float g_k[(size_t)MROWS * KVC];  //  8.4 MB
__device__ float g_v[(size_t)MROWS * KVC];  //  8.4 MB
__device__ float g_y[(size_t)MROWS * CC];   // 33.5 MB

// ---------------------------------------------------------------------------
// SGEMM: C = A(MxK) @ B(KxN), all row-major fp32. BM=BN=128, BK=8, 8x8/thread.
// ---------------------------------------------------------------------------
__global__ __launch_bounds__(256) void sgemm_kernel(
    int M, int N, int K,
    const float* __restrict__ A, const float* __restrict__ B,
    float* __restrict__ C)
{
    constexpr int BM = 128, BN = 128, BK = 8;
    __shared__ float As[BK * BM];   // transposed: As[k][m]
    __shared__ float Bs[BK * BN];   // Bs[k][n]

    const int tid = threadIdx.x;
    const int threadRow = tid / 16;         // 0..15
    const int threadCol = tid % 16;         // 0..15

    const size_t arow0 = (size_t)blockIdx.y * BM;
    const size_t bcol0 = (size_t)blockIdx.x * BN;

    const int aRow = tid / 2;               // 0..127
    const int aCol = (tid % 2) * 4;         // 0 or 4
    const int bRow = tid / 32;              // 0..7
    const int bCol = (tid % 32) * 4;        // 0..124

    float acc[8][8];
    #pragma unroll
    for (int i = 0; i < 8; ++i)
        #pragma unroll
        for (int j = 0; j < 8; ++j) acc[i][j] = 0.0f;

    float regM[8], regN[8];

    for (int k0 = 0; k0 < K; k0 += BK) {
        float4 av = *(const float4*)&A[(arow0 + aRow) * (size_t)K + k0 + aCol];
        As[(aCol + 0) * BM + aRow] = av.x;
        As[(aCol + 1) * BM + aRow] = av.y;
        As[(aCol + 2) * BM + aRow] = av.z;
        As[(aCol + 3) * BM + aRow] = av.w;
        *(float4*)&Bs[bRow * BN + bCol] =
            *(const float4*)&B[(size_t)(k0 + bRow) * N + bcol0 + bCol];
        __syncthreads();

        #pragma unroll
        for (int k = 0; k < BK; ++k) {
            *(float4*)&regM[0] = *(float4*)&As[k * BM + threadRow * 8];
            *(float4*)&regM[4] = *(float4*)&As[k * BM + threadRow * 8 + 4];
            *(float4*)&regN[0] = *(float4*)&Bs[k * BN + threadCol * 8];
            *(float4*)&regN[4] = *(float4*)&Bs[k * BN + threadCol * 8 + 4];
            #pragma unroll
            for (int i = 0; i < 8; ++i)
                #pragma unroll
                for (int j = 0; j < 8; ++j)
                    acc[i][j] = fmaf(regM[i], regN[j], acc[i][j]);
        }
        __syncthreads();
    }

    #pragma unroll
    for (int i = 0; i < 8; ++i) {
        size_t crow = arow0 + threadRow * 8 + i;
        *(float4*)&C[crow * (size_t)N + bcol0 + threadCol * 8]     = *(float4*)&acc[i][0];
        *(float4*)&C[crow * (size_t)N + bcol0 + threadCol * 8 + 4] = *(float4*)&acc[i][4];
    }
}

// ---------------------------------------------------------------------------
// RoPE (in place, first RR dims of each head): rotate-half convention
// ---------------------------------------------------------------------------
__global__ void rope_kernel(float* __restrict__ buf,
                            const float* __restrict__ cosb,
                            const float* __restrict__ sinb,
                            int nh, int pitch, int total)
{
    int idx = blockIdx.x * blockDim.x + threadIdx.x;
    if (idx >= total) return;
    constexpr int RH = RR / 2;
    int r   = idx % RH;
    int h   = (idx / RH) % nh;
    int row = idx / (RH * nh);      // b*T + t
    int t   = row % TT;

    float* p = buf + (size_t)row * pitch + h * DD;
    float c1 = cosb[t * RR + r],       s1 = sinb[t * RR + r];
    float c2 = cosb[t * RR + r + RH],  s2 = sinb[t * RR + r + RH];
    float x1 = p[r], x2 = p[r + RH];
    p[r]      = x1 * c1 - x2 * s1;     // first half: q*cos + (-t2)*sin
    p[r + RH] = x2 * c2 + x1 * s2;     // second half: q*cos + (t1)*sin
}

// ---------------------------------------------------------------------------
// Two-pass causal attention with threshold gating.
// Block = (query tile of 64) x (b,h). 256 threads.
// Pass 1: online (m, l). Pass 2: recompute S, p=exp(s-m)/l, zero if p<thr, P@V.
// ---------------------------------------------------------------------------
constexpr int BQ  = 64;
constexpr int BKT = 64;
constexpr int QP  = 129;   // smem pitch for 128-wide tiles (odd -> conflict-free)
constexpr int PP  = 65;    // smem pitch for P tile
constexpr int RDP = 17;    // reduction pitch
constexpr int ATT_SMEM_FLOATS = 3 * BQ * QP + BQ * PP + BQ * RDP + 4 * BQ;
constexpr int ATT_SMEM_BYTES  = ATT_SMEM_FLOATS * 4;   // 121088

__global__ __launch_bounds__(256, 1) void attn_kernel(
    const float* __restrict__ Q, const float* __restrict__ Km,
    const float* __restrict__ Vm, const float* __restrict__ gate,
    float* __restrict__ Y)
{
    extern __shared__ float sm[];
    float* Qs  = sm;                     // [64][129]
    float* Ks  = Qs + BQ * QP;           // [64][129]
    float* Vs  = Ks + BQ * QP;           // [64][129]
    float* Ps  = Vs + BQ * QP;           // [64][65]
    float* red = Ps + BQ * PP;           // [64][17]
    float* m_s = red + BQ * RDP;         // [64]
    float* l_s = m_s + BQ;               // [64]
    float* mn_s = l_s + BQ;              // [64]
    float* li_s = mn_s + BQ;             // [64]

    const int qt = blockIdx.x;
    const int bh = blockIdx.y;
    const int b  = bh / HH;
    const int h  = bh % HH;
    const int q0 = qt * BQ;
    const int tid = threadIdx.x;
    const int ty = tid / 16;             // 0..15
    const int tx = tid % 16;             // 0..15

    const float scale = 0.08838834764831845f;   // 128^-0.5
    const float thr = 1.0f / (1.0f + __expf(-gate[h]));

    const float* Qb = Q  + (size_t)(b * TT) * CC  + h * DD;
    const float* Kb = Km + (size_t)(b * TT) * KVC + (h / REP) * DD;
    const float* Vb = Vm + (size_t)(b * TT) * KVC + (h / REP) * DD;

    // Load Q tile (rows q0..q0+63, 128 dims)
    for (int e = tid; e < BQ * DD; e += 256) {
        int r = e >> 7, d = e & 127;
        Qs[r * QP + d] = Qb[(size_t)(q0 + r) * CC + d];
    }
    if (tid < BQ) { m_s[tid] = -1e30f; l_s[tid] = 0.0f; }
    __syncthreads();

    // ---------------- PASS 1: compute m, l ----------------
    for (int kt = 0; kt <= qt; ++kt) {
        const int s0 = kt * BKT;
        for (int e = tid; e < BKT * DD; e += 256) {
            int r = e >> 7, d = e & 127;
            Ks[r * QP + d] = Kb[(size_t)(s0 + r) * KVC + d];
        }
        __syncthreads();

        float acc[4][4];
        #pragma unroll
        for (int i = 0; i < 4; ++i)
            #pragma unroll
            for (int j = 0; j < 4; ++j) acc[i][j] = 0.0f;

        for (int d = 0; d < DD; ++d) {
            float a[4], bb[4];
            #pragma unroll
            for (int i = 0; i < 4; ++i) a[i]  = Qs[(ty + 16 * i) * QP + d];
            #pragma unroll
            for (int j = 0; j < 4; ++j) bb[j] = Ks[(tx + 16 * j) * QP + d];
            #pragma unroll
            for (int i = 0; i < 4; ++i)
                #pragma unroll
                for (int j = 0; j < 4; ++j)
                    acc[i][j] = fmaf(a[i], bb[j], acc[i][j]);
        }
        // scale + causal mask, then per-thread row maxima
        #pragma unroll
        for (int i = 0; i < 4; ++i) {
            const int r = ty + 16 * i;
            float pm = -1e30f;
            #pragma unroll
            for (int j = 0; j < 4; ++j) {
                const int c = tx + 16 * j;
                float s = acc[i][j] * scale;
                if (kt == qt && c > r) s = -1e30f;
                acc[i][j] = s;
                pm = fmaxf(pm, s);
            }
            red[r * RDP + tx] = pm;
        }
        __syncthreads();

        float mo = 0.0f, mn = 0.0f;
        if (tid < BQ) {
            float tm = red[tid * RDP];
            #pragma unroll
            for (int k = 1; k < 16; ++k) tm = fmaxf(tm, red[tid * RDP + k]);
            mo = m_s[tid];
            mn = fmaxf(mo, tm);
            mn_s[tid] = mn;
        }
        __syncthreads();

        #pragma unroll
        for (int i = 0; i < 4; ++i) {
            const int r = ty + 16 * i;
            const float mr = mn_s[r];
            float ps = 0.0f;
            #pragma unroll
            for (int j = 0; j < 4; ++j) ps += __expf(acc[i][j] - mr);
            red[r * RDP + tx] = ps;
        }
        __syncthreads();

        if (tid < BQ) {
            float ts = 0.0f;
            #pragma unroll
            for (int k = 0; k < 16; ++k) ts += red[tid * RDP + k];
            l_s[tid] = l_s[tid] * __expf(mo - mn) + ts;
            m_s[tid] = mn;
        }
        __syncthreads();
    }

    if (tid < BQ) li_s[tid] = 1.0f / l_s[tid];
    __syncthreads();

    // ---------------- PASS 2: recompute S, threshold, P @ V ----------------
    float o[4][8];
    #pragma unroll
    for (int i = 0; i < 4; ++i)
        #pragma unroll
        for (int j = 0; j < 8; ++j) o[i][j] = 0.0f;

    for (int kt = 0; kt <= qt; ++kt) {
        const int s0 = kt * BKT;
        for (int e = tid; e < BKT * DD; e += 256) {
            int r = e >> 7, d = e & 127;
            Ks[r * QP + d] = Kb[(size_t)(s0 + r) * KVC + d];
            Vs[r * QP + d] = Vb[(size_t)(s0 + r) * KVC + d];
        }
        __syncthreads();

        float acc[4][4];
        #pragma unroll
        for (int i = 0; i < 4; ++i)
            #pragma unroll
            for (int j = 0; j < 4; ++j) acc[i][j] = 0.0f;

        for (int d = 0; d < DD; ++d) {
            float a[4], bb[4];
            #pragma unroll
            for (int i = 0; i < 4; ++i) a[i]  = Qs[(ty + 16 * i) * QP + d];
            #pragma unroll
            for (int j = 0; j < 4; ++j) bb[j] = Ks[(tx + 16 * j) * QP + d];
            #pragma unroll
            for (int i = 0; i < 4; ++i)
                #pragma unroll
                for (int j = 0; j < 4; ++j)
                    acc[i][j] = fmaf(a[i], bb[j], acc[i][j]);
        }

        #pragma unroll
        for (int i = 0; i < 4; ++i) {
            const int r = ty + 16 * i;
            const float mr = m_s[r];
            const float li = li_s[r];
            #pragma unroll
            for (int j = 0; j < 4; ++j) {
                const int c = tx + 16 * j;
                float s = acc[i][j] * scale;
                if (kt == qt && c > r) s = -1e30f;
                float p = __expf(s - mr) * li;
                if (p < thr) p = 0.0f;
                Ps[r * PP + c] = p;
            }
        }
        __syncthreads();

        for (int s = 0; s < BKT; ++s) {
            float pv[4], vv[8];
            #pragma unroll
            for (int i = 0; i < 4; ++i) pv[i] = Ps[(ty + 16 * i) * PP + s];
            #pragma unroll
            for (int j = 0; j < 8; ++j) vv[j] = Vs[s * QP + tx + 16 * j];
            #pragma unroll
            for (int i = 0; i < 4; ++i)
                #pragma unroll
                for (int j = 0; j < 8; ++j)
                    o[i][j] = fmaf(pv[i], vv[j], o[i][j]);
        }
        __syncthreads();
    }

    // Write Y in (B,T,H*D) layout
    #pragma unroll
    for (int i = 0; i < 4; ++i) {
        const int r = ty + 16 * i;
        #pragma unroll
        for (int j = 0; j < 8; ++j) {
            const int c = tx + 16 * j;
            Y[(size_t)(b * TT + q0 + r) * CC + h * DD + c] = o[i][j];
        }
    }
}

// ---------------------------------------------------------------------------
// Launch
// ---------------------------------------------------------------------------
extern "C" void kernel_launch(void* const* d_in, const int* in_sizes, int n_in,
                              void* d_out, int out_size)
{
    const float* x    = (const float*)d_in[0];
    const float* cosb = (const float*)d_in[1];
    const float* sinb = (const float*)d_in[2];
    const float* Wq   = (const float*)d_in[3];
    const float* Wk   = (const float*)d_in[4];
    const float* Wv   = (const float*)d_in[5];
    const float* Wo   = (const float*)d_in[6];
    const float* gate = (const float*)d_in[7];
    float* out = (float*)d_out;

    float *q, *k, *v, *y;
    cudaGetSymbolAddress((void**)&q, g_q);
    cudaGetSymbolAddress((void**)&k, g_k);
    cudaGetSymbolAddress((void**)&v, g_v);
    cudaGetSymbolAddress((void**)&y, g_y);

    // Projections
    sgemm_kernel<<<dim3(CC / 128, MROWS / 128), 256>>>(MROWS, CC,  CC, x, Wq, q);
    sgemm_kernel<<<dim3(KVC / 128, MROWS / 128), 256>>>(MROWS, KVC, CC, x, Wk, k);
    sgemm_kernel<<<dim3(KVC / 128, MROWS / 128), 256>>>(MROWS, KVC, CC, x, Wv, v);

    // RoPE (in place)
    {
        int totq = BB * TT * HH   * (RR / 2);
        int totk = BB * TT * HKVV * (RR / 2);
        rope_kernel<<<(totq + 255) / 256, 256>>>(q, cosb, sinb, HH,   CC,  totq);
        rope_kernel<<<(totk + 255) / 256, 256>>>(k, cosb, sinb, HKVV, KVC, totk);
    }

    // Attention
    static bool attr_set = false;
    if (!attr_set) {
        cudaFuncSetAttribute(attn_kernel,
                             cudaFuncAttributeMaxDynamicSharedMemorySize,
                             ATT_SMEM_BYTES);
        attr_set = true;
    }
    attn_kernel<<<dim3(TT / BQ, BB * HH), 256, ATT_SMEM_BYTES>>>(q, k, v, gate, y);

    // Output projection
    sgemm_kernel<<<dim3(CC / 128, MROWS / 128), 256>>>(MROWS, CC, CC, y, Wo, out);
}

// round 5
// speedup vs baseline: 1.1874x; 1.1874x over previous
#include <cuda_runtime.h>
#include <cuda_bf16.h>
#include <cstdint>
#include <stdint.h>
#include <math.h>

// Problem constants
constexpr int BB  = 2;
constexpr int TT  = 2048;
constexpr int CC  = 2048;
constexpr int HH  = 16;
constexpr int HKVV = 4;
constexpr int DD  = 128;
constexpr int RR  = 64;
constexpr int KVC = HKVV * DD;      // 512
constexpr int REP = HH / HKVV;      // 4
constexpr int MROWS = BB * TT;      // 4096

// ---------------------------------------------------------------------------
// Scratch (static __device__ arrays; no allocations allowed)
// ---------------------------------------------------------------------------
__device__ float g_q[(size_t)MROWS * CC];   // 33.5 MB
__device__ float g_k[(size_t)MROWS * KVC];  //  8.4 MB
__device__ float g_v[(size_t)MROWS * KVC];  //  8.4 MB
__device__ float g_y[(size_t)MROWS * CC];   // 33.5 MB

// ---------------------------------------------------------------------------
// tf32 helpers (tf32x3 split: x = hi + lo, both tf32; drop lo*lo term)
// ---------------------------------------------------------------------------
__device__ __forceinline__ void split_tf32(float f, unsigned int& hi, unsigned int& lo) {
    asm("cvt.rna.tf32.f32 %0, %1;" : "=r"(hi) : "f"(f));
    float hif = __uint_as_float(hi);
    float lof = f - hif;
    asm("cvt.rna.tf32.f32 %0, %1;" : "=r"(lo) : "f"(lof));
}

__device__ __forceinline__ void cp16(void* smem_ptr, const void* gptr) {
    unsigned int s = (unsigned int)__cvta_generic_to_shared(smem_ptr);
    asm volatile("cp.async.cg.shared.global [%0], [%1], 16;" :: "r"(s), "l"(gptr));
}

__device__ __forceinline__ void mma_tf32(float* d, const unsigned int* a, const unsigned int* b) {
    asm volatile(
        "mma.sync.aligned.m16n8k8.row.col.f32.tf32.tf32.f32 "
        "{%0,%1,%2,%3}, {%4,%5,%6,%7}, {%8,%9}, {%0,%1,%2,%3};"
        : "+f"(d[0]), "+f"(d[1]), "+f"(d[2]), "+f"(d[3])
        : "r"(a[0]), "r"(a[1]), "r"(a[2]), "r"(a[3]), "r"(b[0]), "r"(b[1]));
}

// ---------------------------------------------------------------------------
// tf32x3 tensor-core GEMM: C = A(MxK) @ B(KxN), row-major fp32 in/out.
// Block tile 128x128x16, 8 warps (2x4), warp tile 64x32, m16n8k8 MMA.
// Each product accumulated as hi*hi + lo*hi + hi*lo  (~fp32 precision).
// cp.async double-buffered smem. A pitch 20, B pitch 136 (conflict-free).
// ---------------------------------------------------------------------------
__global__ __launch_bounds__(256) void tgemm_kernel(
    int M, int N, int K,
    const float* __restrict__ A, const float* __restrict__ B,
    float* __restrict__ C)
{
    constexpr int BM = 128, BN = 128, BK = 16, AP = 20, BP = 136;
    __shared__ float As[2][BM * AP];   // [m][k], pitch 20
    __shared__ float Bs[2][BK * BP];   // [k][n], pitch 136

    const int tid  = threadIdx.x;
    const int lane = tid & 31;
    const int w    = tid >> 5;
    const int wm   = w >> 2;            // 0..1
    const int wn   = w & 3;             // 0..3
    const int grp  = lane >> 2;         // 0..7
    const int qid  = lane & 3;          // 0..3

    const size_t bm = (size_t)blockIdx.y * BM;
    const size_t bn = (size_t)blockIdx.x * BN;

    float acc[4][4][4];
    #pragma unroll
    for (int i = 0; i < 4; ++i)
        #pragma unroll
        for (int j = 0; j < 4; ++j)
            #pragma unroll
            for (int c = 0; c < 4; ++c) acc[i][j][c] = 0.0f;

    auto load_stage = [&](int k0, int buf) {
        #pragma unroll
        for (int c = 0; c < 2; ++c) {              // A: 512 x 16B chunks
            int idx = tid + c * 256;
            int row = idx >> 2, col = (idx & 3) * 4;
            cp16(&As[buf][row * AP + col], &A[(bm + row) * (size_t)K + k0 + col]);
        }
        #pragma unroll
        for (int c = 0; c < 2; ++c) {              // B: 512 x 16B chunks
            int idx = tid + c * 256;
            int row = idx >> 5, col = (idx & 31) * 4;
            cp16(&Bs[buf][row * BP + col], &B[(size_t)(k0 + row) * N + bn + col]);
        }
    };

    load_stage(0, 0);
    asm volatile("cp.async.commit_group;");

    const int nst = K / BK;
    for (int s = 0; s < nst; ++s) {
        asm volatile("cp.async.wait_group 0;");
        __syncthreads();
        const int cur = s & 1;
        if (s + 1 < nst) {
            load_stage((s + 1) * BK, cur ^ 1);
            asm volatile("cp.async.commit_group;");
        }

        const float* Asb = As[cur];
        const float* Bsb = Bs[cur];
        #pragma unroll
        for (int ks = 0; ks < BK; ks += 8) {
            unsigned int afh[4][4], afl[4][4], bfh[4][2], bfl[4][2];
            #pragma unroll
            for (int mt = 0; mt < 4; ++mt) {
                int r0 = wm * 64 + mt * 16 + grp;
                split_tf32(Asb[r0 * AP + ks + qid],           afh[mt][0], afl[mt][0]);
                split_tf32(Asb[(r0 + 8) * AP + ks + qid],     afh[mt][1], afl[mt][1]);
                split_tf32(Asb[r0 * AP + ks + qid + 4],       afh[mt][2], afl[mt][2]);
                split_tf32(Asb[(r0 + 8) * AP + ks + qid + 4], afh[mt][3], afl[mt][3]);
            }
            #pragma unroll
            for (int nt = 0; nt < 4; ++nt) {
                int c0 = wn * 32 + nt * 8 + grp;
                split_tf32(Bsb[(ks + qid) * BP + c0],     bfh[nt][0], bfl[nt][0]);
                split_tf32(Bsb[(ks + qid + 4) * BP + c0], bfh[nt][1], bfl[nt][1]);
            }
            #pragma unroll
            for (int mt = 0; mt < 4; ++mt)
                #pragma unroll
                for (int nt = 0; nt < 4; ++nt) {
                    mma_tf32(acc[mt][nt], afl[mt], bfh[nt]);   // lo*hi
                    mma_tf32(acc[mt][nt], afh[mt], bfl[nt]);   // hi*lo
                    mma_tf32(acc[mt][nt], afh[mt], bfh[nt]);   // hi*hi
                }
        }
        __syncthreads();
    }

    // Epilogue: c0,c1 at (row, 2q),(row, 2q+1); c2,c3 at (row+8, ...)
    #pragma unroll
    for (int mt = 0; mt < 4; ++mt) {
        #pragma unroll
        for (int nt = 0; nt < 4; ++nt) {
            size_t r  = bm + wm * 64 + mt * 16 + grp;
            size_t c0 = bn + wn * 32 + nt * 8 + 2 * qid;
            *(float2*)&C[r * (size_t)N + c0]       = make_float2(acc[mt][nt][0], acc[mt][nt][1]);
            *(float2*)&C[(r + 8) * (size_t)N + c0] = make_float2(acc[mt][nt][2], acc[mt][nt][3]);
        }
    }
}

// ---------------------------------------------------------------------------
// RoPE (in place, first RR dims of each head): rotate-half convention
// ---------------------------------------------------------------------------
__global__ void rope_kernel(float* __restrict__ buf,
                            const float* __restrict__ cosb,
                            const float* __restrict__ sinb,
                            int nh, int pitch, int total)
{
    int idx = blockIdx.x * blockDim.x + threadIdx.x;
    if (idx >= total) return;
    constexpr int RH = RR / 2;
    int r   = idx % RH;
    int h   = (idx / RH) % nh;
    int row = idx / (RH * nh);      // b*T + t
    int t   = row % TT;

    float* p = buf + (size_t)row * pitch + h * DD;
    float c1 = cosb[t * RR + r],       s1 = sinb[t * RR + r];
    float c2 = cosb[t * RR + r + RH],  s2 = sinb[t * RR + r + RH];
    float x1 = p[r], x2 = p[r + RH];
    p[r]      = x1 * c1 - x2 * s1;
    p[r + RH] = x2 * c2 + x1 * s2;
}

// ---------------------------------------------------------------------------
// Two-pass causal attention with threshold gating.
// ---------------------------------------------------------------------------
constexpr int BQ  = 64;
constexpr int BKT = 64;
constexpr int QP  = 129;
constexpr int PP  = 65;
constexpr int RDP = 17;
constexpr int ATT_SMEM_FLOATS = 3 * BQ * QP + BQ * PP + BQ * RDP + 4 * BQ;
constexpr int ATT_SMEM_BYTES  = ATT_SMEM_FLOATS * 4;   // 121088

__global__ __launch_bounds__(256, 1) void attn_kernel(
    const float* __restrict__ Q, const float* __restrict__ Km,
    const float* __restrict__ Vm, const float* __restrict__ gate,
    float* __restrict__ Y)
{
    extern __shared__ float sm[];
    float* Qs  = sm;
    float* Ks  = Qs + BQ * QP;
    float* Vs  = Ks + BQ * QP;
    float* Ps  = Vs + BQ * QP;
    float* red = Ps + BQ * PP;
    float* m_s = red + BQ * RDP;
    float* l_s = m_s + BQ;
    float* mn_s = l_s + BQ;
    float* li_s = mn_s + BQ;

    const int qt = blockIdx.x;
    const int bh = blockIdx.y;
    const int b  = bh / HH;
    const int h  = bh % HH;
    const int q0 = qt * BQ;
    const int tid = threadIdx.x;
    const int ty = tid / 16;
    const int tx = tid % 16;

    const float scale = 0.08838834764831845f;
    const float thr = 1.0f / (1.0f + __expf(-gate[h]));

    const float* Qb = Q  + (size_t)(b * TT) * CC  + h * DD;
    const float* Kb = Km + (size_t)(b * TT) * KVC + (h / REP) * DD;
    const float* Vb = Vm + (size_t)(b * TT) * KVC + (h / REP) * DD;

    for (int e = tid; e < BQ * DD; e += 256) {
        int r = e >> 7, d = e & 127;
        Qs[r * QP + d] = Qb[(size_t)(q0 + r) * CC + d];
    }
    if (tid < BQ) { m_s[tid] = -1e30f; l_s[tid] = 0.0f; }
    __syncthreads();

    // ---------------- PASS 1: compute m, l ----------------
    for (int kt = 0; kt <= qt; ++kt) {
        const int s0 = kt * BKT;
        for (int e = tid; e < BKT * DD; e += 256) {
            int r = e >> 7, d = e & 127;
            Ks[r * QP + d] = Kb[(size_t)(s0 + r) * KVC + d];
        }
        __syncthreads();

        float acc[4][4];
        #pragma unroll
        for (int i = 0; i < 4; ++i)
            #pragma unroll
            for (int j = 0; j < 4; ++j) acc[i][j] = 0.0f;

        for (int d = 0; d < DD; ++d) {
            float a[4], bb[4];
            #pragma unroll
            for (int i = 0; i < 4; ++i) a[i]  = Qs[(ty + 16 * i) * QP + d];
            #pragma unroll
            for (int j = 0; j < 4; ++j) bb[j] = Ks[(tx + 16 * j) * QP + d];
            #pragma unroll
            for (int i = 0; i < 4; ++i)
                #pragma unroll
                for (int j = 0; j < 4; ++j)
                    acc[i][j] = fmaf(a[i], bb[j], acc[i][j]);
        }
        #pragma unroll
        for (int i = 0; i < 4; ++i) {
            const int r = ty + 16 * i;
            float pm = -1e30f;
            #pragma unroll
            for (int j = 0; j < 4; ++j) {
                const int c = tx + 16 * j;
                float s = acc[i][j] * scale;
                if (kt == qt && c > r) s = -1e30f;
                acc[i][j] = s;
                pm = fmaxf(pm, s);
            }
            red[r * RDP + tx] = pm;
        }
        __syncthreads();

        float mo = 0.0f, mn = 0.0f;
        if (tid < BQ) {
            float tm = red[tid * RDP];
            #pragma unroll
            for (int k = 1; k < 16; ++k) tm = fmaxf(tm, red[tid * RDP + k]);
            mo = m_s[tid];
            mn = fmaxf(mo, tm);
            mn_s[tid] = mn;
        }
        __syncthreads();

        #pragma unroll
        for (int i = 0; i < 4; ++i) {
            const int r = ty + 16 * i;
            const float mr = mn_s[r];
            float ps = 0.0f;
            #pragma unroll
            for (int j = 0; j < 4; ++j) ps += __expf(acc[i][j] - mr);
            red[r * RDP + tx] = ps;
        }
        __syncthreads();

        if (tid < BQ) {
            float ts = 0.0f;
            #pragma unroll
            for (int k = 0; k < 16; ++k) ts += red[tid * RDP + k];
            l_s[tid] = l_s[tid] * __expf(mo - mn) + ts;
            m_s[tid] = mn;
        }
        __syncthreads();
    }

    if (tid < BQ) li_s[tid] = 1.0f / l_s[tid];
    __syncthreads();

    // ---------------- PASS 2: recompute S, threshold, P @ V ----------------
    float o[4][8];
    #pragma unroll
    for (int i = 0; i < 4; ++i)
        #pragma unroll
        for (int j = 0; j < 8; ++j) o[i][j] = 0.0f;

    for (int kt = 0; kt <= qt; ++kt) {
        const int s0 = kt * BKT;
        for (int e = tid; e < BKT * DD; e += 256) {
            int r = e >> 7, d = e & 127;
            Ks[r * QP + d] = Kb[(size_t)(s0 + r) * KVC + d];
            Vs[r * QP + d] = Vb[(size_t)(s0 + r) * KVC + d];
        }
        __syncthreads();

        float acc[4][4];
        #pragma unroll
        for (int i = 0; i < 4; ++i)
            #pragma unroll
            for (int j = 0; j < 4; ++j) acc[i][j] = 0.0f;

        for (int d = 0; d < DD; ++d) {
            float a[4], bb[4];
            #pragma unroll
            for (int i = 0; i < 4; ++i) a[i]  = Qs[(ty + 16 * i) * QP + d];
            #pragma unroll
            for (int j = 0; j < 4; ++j) bb[j] = Ks[(tx + 16 * j) * QP + d];
            #pragma unroll
            for (int i = 0; i < 4; ++i)
                #pragma unroll
                for (int j = 0; j < 4; ++j)
                    acc[i][j] = fmaf(a[i], bb[j], acc[i][j]);
        }

        #pragma unroll
        for (int i = 0; i < 4; ++i) {
            const int r = ty + 16 * i;
            const float mr = m_s[r];
            const float li = li_s[r];
            #pragma unroll
            for (int j = 0; j < 4; ++j) {
                const int c = tx + 16 * j;
                float s = acc[i][j] * scale;
                if (kt == qt && c > r) s = -1e30f;
                float p = __expf(s - mr) * li;
                if (p < thr) p = 0.0f;
                Ps[r * PP + c] = p;
            }
        }
        __syncthreads();

        for (int s = 0; s < BKT; ++s) {
            float pv[4], vv[8];
            #pragma unroll
            for (int i = 0; i < 4; ++i) pv[i] = Ps[(ty + 16 * i) * PP + s];
            #pragma unroll
            for (int j = 0; j < 8; ++j) vv[j] = Vs[s * QP + tx + 16 * j];
            #pragma unroll
            for (int i = 0; i < 4; ++i)
                #pragma unroll
                for (int j = 0; j < 8; ++j)
                    o[i][j] = fmaf(pv[i], vv[j], o[i][j]);
        }
        __syncthreads();
    }

    #pragma unroll
    for (int i = 0; i < 4; ++i) {
        const int r = ty + 16 * i;
        #pragma unroll
        for (int j = 0; j < 8; ++j) {
            const int c = tx + 16 * j;
            Y[(size_t)(b * TT + q0 + r) * CC + h * DD + c] = o[i][j];
        }
    }
}

// ---------------------------------------------------------------------------
// Launch
// ---------------------------------------------------------------------------
extern "C" void kernel_launch(void* const* d_in, const int* in_sizes, int n_in,
                              void* d_out, int out_size)
{
    const float* x    = (const float*)d_in[0];
    const float* cosb = (const float*)d_in[1];
    const float* sinb = (const float*)d_in[2];
    const float* Wq   = (const float*)d_in[3];
    const float* Wk   = (const float*)d_in[4];
    const float* Wv   = (const float*)d_in[5];
    const float* Wo   = (const float*)d_in[6];
    const float* gate = (const float*)d_in[7];
    float* out = (float*)d_out;

    float *q, *k, *v, *y;
    cudaGetSymbolAddress((void**)&q, g_q);
    cudaGetSymbolAddress((void**)&k, g_k);
    cudaGetSymbolAddress((void**)&v, g_v);
    cudaGetSymbolAddress((void**)&y, g_y);

    // Projections (tf32x3 tensor cores)
    tgemm_kernel<<<dim3(CC / 128, MROWS / 128), 256>>>(MROWS, CC,  CC, x, Wq, q);
    tgemm_kernel<<<dim3(KVC / 128, MROWS / 128), 256>>>(MROWS, KVC, CC, x, Wk, k);
    tgemm_kernel<<<dim3(KVC / 128, MROWS / 128), 256>>>(MROWS, KVC, CC, x, Wv, v);

    // RoPE (in place)
    {
        int totq = BB * TT * HH   * (RR / 2);
        int totk = BB * TT * HKVV * (RR / 2);
        rope_kernel<<<(totq + 255) / 256, 256>>>(q, cosb, sinb, HH,   CC,  totq);
        rope_kernel<<<(totk + 255) / 256, 256>>>(k, cosb, sinb, HKVV, KVC, totk);
    }

    // Attention
    static bool attr_set = false;
    if (!attr_set) {
        cudaFuncSetAttribute(attn_kernel,
                             cudaFuncAttributeMaxDynamicSharedMemorySize,
                             ATT_SMEM_BYTES);
        attr_set = true;
    }
    attn_kernel<<<dim3(TT / BQ, BB * HH), 256, ATT_SMEM_BYTES>>>(q, k, v, gate, y);

    // Output projection (tf32x3 tensor cores)
    tgemm_kernel<<<dim3(CC / 128, MROWS / 128), 256>>>(MROWS, CC, CC, y, Wo, out);
}

// round 7
// speedup vs baseline: 1.5391x; 1.2963x over previous
#include <cuda_runtime.h>
#include <cuda_bf16.h>
#include <cstdint>
#include <stdint.h>
#include <math.h>

// Problem constants
constexpr int BB  = 2;
constexpr int TT  = 2048;
constexpr int CC  = 2048;
constexpr int HH  = 16;
constexpr int HKVV = 4;
constexpr int DD  = 128;
constexpr int RR  = 64;
constexpr int KVC = HKVV * DD;      // 512
constexpr int REP = HH / HKVV;      // 4
constexpr int MROWS = BB * TT;      // 4096

// ---------------------------------------------------------------------------
// Scratch (static __device__ arrays; no allocations allowed)
// ---------------------------------------------------------------------------
__device__ float g_q[(size_t)MROWS * CC];            // 33.5 MB
__device__ float g_k[(size_t)MROWS * KVC];           //  8.4 MB
__device__ float g_v[(size_t)MROWS * KVC];           //  8.4 MB
__device__ float g_y[(size_t)MROWS * CC];            // 33.5 MB
__device__ float g_s[(size_t)BB * HH * TT * TT];     // 537 MB — S stash

// ---------------------------------------------------------------------------
// tf32 helpers
// ---------------------------------------------------------------------------
__device__ __forceinline__ unsigned int f2tf(float f) {
    unsigned int r;
    asm("cvt.rna.tf32.f32 %0, %1;" : "=r"(r) : "f"(f));
    return r;
}

__device__ __forceinline__ void split_tf32(float f, unsigned int& hi, unsigned int& lo) {
    asm("cvt.rna.tf32.f32 %0, %1;" : "=r"(hi) : "f"(f));
    float hif = __uint_as_float(hi);
    float lof = f - hif;
    asm("cvt.rna.tf32.f32 %0, %1;" : "=r"(lo) : "f"(lof));
}

__device__ __forceinline__ void cp16(void* smem_ptr, const void* gptr) {
    unsigned int s = (unsigned int)__cvta_generic_to_shared(smem_ptr);
    asm volatile("cp.async.cg.shared.global [%0], [%1], 16;" :: "r"(s), "l"(gptr));
}

__device__ __forceinline__ void mma_tf32(float* d, const unsigned int* a, const unsigned int* b) {
    asm volatile(
        "mma.sync.aligned.m16n8k8.row.col.f32.tf32.tf32.f32 "
        "{%0,%1,%2,%3}, {%4,%5,%6,%7}, {%8,%9}, {%0,%1,%2,%3};"
        : "+f"(d[0]), "+f"(d[1]), "+f"(d[2]), "+f"(d[3])
        : "r"(a[0]), "r"(a[1]), "r"(a[2]), "r"(a[3]), "r"(b[0]), "r"(b[1]));
}

// ---------------------------------------------------------------------------
// tf32 tensor-core GEMM, templated on SPLIT:
//   SPLIT=3 -> tf32x3 (hi*hi + lo*hi + hi*lo, ~fp32 precision)
//   SPLIT=1 -> single tf32 (fast; ~3e-4 rel err — smooth paths only)
// Block tile 128x128x16, 8 warps (2x4), warp tile 64x32, m16n8k8 MMA.
// cp.async double-buffered smem. A pitch 20, B pitch 136 (conflict-free).
// ---------------------------------------------------------------------------
template <int SPLIT>
__global__ __launch_bounds__(256) void tgemm_kernel(
    int M, int N, int K,
    const float* __restrict__ A, const float* __restrict__ B,
    float* __restrict__ C)
{
    constexpr int BM = 128, BN = 128, BK = 16, AP = 20, BP = 136;
    __shared__ float As[2][BM * AP];   // [m][k], pitch 20
    __shared__ float Bs[2][BK * BP];   // [k][n], pitch 136

    const int tid  = threadIdx.x;
    const int lane = tid & 31;
    const int w    = tid >> 5;
    const int wm   = w >> 2;            // 0..1
    const int wn   = w & 3;             // 0..3
    const int grp  = lane >> 2;         // 0..7
    const int qid  = lane & 3;          // 0..3

    const size_t bm = (size_t)blockIdx.y * BM;
    const size_t bn = (size_t)blockIdx.x * BN;

    float acc[4][4][4];
    #pragma unroll
    for (int i = 0; i < 4; ++i)
        #pragma unroll
        for (int j = 0; j < 4; ++j)
            #pragma unroll
            for (int c = 0; c < 4; ++c) acc[i][j][c] = 0.0f;

    auto load_stage = [&](int k0, int buf) {
        #pragma unroll
        for (int c = 0; c < 2; ++c) {              // A: 512 x 16B chunks
            int idx = tid + c * 256;
            int row = idx >> 2, col = (idx & 3) * 4;
            cp16(&As[buf][row * AP + col], &A[(bm + row) * (size_t)K + k0 + col]);
        }
        #pragma unroll
        for (int c = 0; c < 2; ++c) {              // B: 512 x 16B chunks
            int idx = tid + c * 256;
            int row = idx >> 5, col = (idx & 31) * 4;
            cp16(&Bs[buf][row * BP + col], &B[(size_t)(k0 + row) * N + bn + col]);
        }
    };

    load_stage(0, 0);
    asm volatile("cp.async.commit_group;");

    const int nst = K / BK;
    for (int s = 0; s < nst; ++s) {
        asm volatile("cp.async.wait_group 0;");
        __syncthreads();
        const int cur = s & 1;
        if (s + 1 < nst) {
            load_stage((s + 1) * BK, cur ^ 1);
            asm volatile("cp.async.commit_group;");
        }

        const float* Asb = As[cur];
        const float* Bsb = Bs[cur];
        #pragma unroll
        for (int ks = 0; ks < BK; ks += 8) {
            unsigned int afh[4][4], afl[4][4], bfh[4][2], bfl[4][2];
            #pragma unroll
            for (int mt = 0; mt < 4; ++mt) {
                int r0 = wm * 64 + mt * 16 + grp;
                if (SPLIT == 3) {
                    split_tf32(Asb[r0 * AP + ks + qid],           afh[mt][0], afl[mt][0]);
                    split_tf32(Asb[(r0 + 8) * AP + ks + qid],     afh[mt][1], afl[mt][1]);
                    split_tf32(Asb[r0 * AP + ks + qid + 4],       afh[mt][2], afl[mt][2]);
                    split_tf32(Asb[(r0 + 8) * AP + ks + qid + 4], afh[mt][3], afl[mt][3]);
                } else {
                    afh[mt][0] = f2tf(Asb[r0 * AP + ks + qid]);
                    afh[mt][1] = f2tf(Asb[(r0 + 8) * AP + ks + qid]);
                    afh[mt][2] = f2tf(Asb[r0 * AP + ks + qid + 4]);
                    afh[mt][3] = f2tf(Asb[(r0 + 8) * AP + ks + qid + 4]);
                }
            }
            #pragma unroll
            for (int nt = 0; nt < 4; ++nt) {
                int c0 = wn * 32 + nt * 8 + grp;
                if (SPLIT == 3) {
                    split_tf32(Bsb[(ks + qid) * BP + c0],     bfh[nt][0], bfl[nt][0]);
                    split_tf32(Bsb[(ks + qid + 4) * BP + c0], bfh[nt][1], bfl[nt][1]);
                } else {
                    bfh[nt][0] = f2tf(Bsb[(ks + qid) * BP + c0]);
                    bfh[nt][1] = f2tf(Bsb[(ks + qid + 4) * BP + c0]);
                }
            }
            #pragma unroll
            for (int mt = 0; mt < 4; ++mt)
                #pragma unroll
                for (int nt = 0; nt < 4; ++nt) {
                    if (SPLIT == 3) {
                        mma_tf32(acc[mt][nt], afl[mt], bfh[nt]);   // lo*hi
                        mma_tf32(acc[mt][nt], afh[mt], bfl[nt]);   // hi*lo
                    }
                    mma_tf32(acc[mt][nt], afh[mt], bfh[nt]);       // hi*hi
                }
        }
        __syncthreads();
    }

    #pragma unroll
    for (int mt = 0; mt < 4; ++mt) {
        #pragma unroll
        for (int nt = 0; nt < 4; ++nt) {
            size_t r  = bm + wm * 64 + mt * 16 + grp;
            size_t c0 = bn + wn * 32 + nt * 8 + 2 * qid;
            *(float2*)&C[r * (size_t)N + c0]       = make_float2(acc[mt][nt][0], acc[mt][nt][1]);
            *(float2*)&C[(r + 8) * (size_t)N + c0] = make_float2(acc[mt][nt][2], acc[mt][nt][3]);
        }
    }
}

// ---------------------------------------------------------------------------
// RoPE (in place, first RR dims of each head): rotate-half convention
// ---------------------------------------------------------------------------
__global__ void rope_kernel(float* __restrict__ buf,
                            const float* __restrict__ cosb,
                            const float* __restrict__ sinb,
                            int nh, int pitch, int total)
{
    int idx = blockIdx.x * blockDim.x + threadIdx.x;
    if (idx >= total) return;
    constexpr int RH = RR / 2;
    int r   = idx % RH;
    int h   = (idx / RH) % nh;
    int row = idx / (RH * nh);      // b*T + t
    int t   = row % TT;

    float* p = buf + (size_t)row * pitch + h * DD;
    float c1 = cosb[t * RR + r],       s1 = sinb[t * RR + r];
    float c2 = cosb[t * RR + r + RH],  s2 = sinb[t * RR + r + RH];
    float x1 = p[r], x2 = p[r + RH];
    p[r]      = x1 * c1 - x2 * s1;
    p[r + RH] = x2 * c2 + x1 * s2;
}

// ---------------------------------------------------------------------------
// Two-pass causal attention with threshold gating.
// Pass 1: QK once, stash masked S to g_s, online m/l.
// Pass 2: reload S from g_s, p=exp(s-m)/l, threshold, P @ V.
// ---------------------------------------------------------------------------
constexpr int BQ  = 64;
constexpr int BKT = 64;
constexpr int QP  = 129;
constexpr int PP  = 65;
constexpr int RDP = 17;
constexpr int ATT_SMEM_FLOATS = 3 * BQ * QP + BQ * PP + BQ * RDP + 4 * BQ;
constexpr int ATT_SMEM_BYTES  = ATT_SMEM_FLOATS * 4;   // 121088

__global__ __launch_bounds__(256, 1) void attn_kernel(
    const float* __restrict__ Q, const float* __restrict__ Km,
    const float* __restrict__ Vm, const float* __restrict__ gate,
    float* __restrict__ Y)
{
    extern __shared__ float sm[];
    float* Qs  = sm;
    float* Ks  = Qs + BQ * QP;
    float* Vs  = Ks + BQ * QP;
    float* Ps  = Vs + BQ * QP;
    float* red = Ps + BQ * PP;
    float* m_s = red + BQ * RDP;
    float* l_s = m_s + BQ;
    float* mn_s = l_s + BQ;
    float* li_s = mn_s + BQ;

    const int qt = blockIdx.x;
    const int bh = blockIdx.y;
    const int b  = bh / HH;
    const int h  = bh % HH;
    const int q0 = qt * BQ;
    const int tid = threadIdx.x;
    const int ty = tid / 16;
    const int tx = tid % 16;

    const float scale = 0.08838834764831845f;
    const float thr = 1.0f / (1.0f + __expf(-gate[h]));

    const float* Qb = Q  + (size_t)(b * TT) * CC  + h * DD;
    const float* Kb = Km + (size_t)(b * TT) * KVC + (h / REP) * DD;
    const float* Vb = Vm + (size_t)(b * TT) * KVC + (h / REP) * DD;
    float* Sb = g_s + ((size_t)bh * TT + q0) * TT;   // rows q0..q0+63 of S

    for (int e = tid; e < BQ * DD; e += 256) {
        int r = e >> 7, d = e & 127;
        Qs[r * QP + d] = Qb[(size_t)(q0 + r) * CC + d];
    }
    if (tid < BQ) { m_s[tid] = -1e30f; l_s[tid] = 0.0f; }
    __syncthreads();

    // ---------------- PASS 1: QK, stash S, compute m, l ----------------
    for (int kt = 0; kt <= qt; ++kt) {
        const int s0 = kt * BKT;
        for (int e = tid; e < BKT * DD; e += 256) {
            int r = e >> 7, d = e & 127;
            Ks[r * QP + d] = Kb[(size_t)(s0 + r) * KVC + d];
        }
        __syncthreads();

        float acc[4][4];
        #pragma unroll
        for (int i = 0; i < 4; ++i)
            #pragma unroll
            for (int j = 0; j < 4; ++j) acc[i][j] = 0.0f;

        for (int d = 0; d < DD; ++d) {
            float a[4], bb[4];
            #pragma unroll
            for (int i = 0; i < 4; ++i) a[i]  = Qs[(ty + 16 * i) * QP + d];
            #pragma unroll
            for (int j = 0; j < 4; ++j) bb[j] = Ks[(tx + 16 * j) * QP + d];
            #pragma unroll
            for (int i = 0; i < 4; ++i)
                #pragma unroll
                for (int j = 0; j < 4; ++j)
                    acc[i][j] = fmaf(a[i], bb[j], acc[i][j]);
        }
        #pragma unroll
        for (int i = 0; i < 4; ++i) {
            const int r = ty + 16 * i;
            float pm = -1e30f;
            #pragma unroll
            for (int j = 0; j < 4; ++j) {
                const int c = tx + 16 * j;
                float s = acc[i][j] * scale;
                if (kt == qt && c > r) s = -1e30f;
                acc[i][j] = s;
                Sb[(size_t)r * TT + s0 + c] = s;     // stash masked S
                pm = fmaxf(pm, s);
            }
            red[r * RDP + tx] = pm;
        }
        __syncthreads();

        float mo = 0.0f, mn = 0.0f;
        if (tid < BQ) {
            float tm = red[tid * RDP];
            #pragma unroll
            for (int k = 1; k < 16; ++k) tm = fmaxf(tm, red[tid * RDP + k]);
            mo = m_s[tid];
            mn = fmaxf(mo, tm);
            mn_s[tid] = mn;
        }
        __syncthreads();

        #pragma unroll
        for (int i = 0; i < 4; ++i) {
            const int r = ty + 16 * i;
            const float mr = mn_s[r];
            float ps = 0.0f;
            #pragma unroll
            for (int j = 0; j < 4; ++j) ps += __expf(acc[i][j] - mr);
            red[r * RDP + tx] = ps;
        }
        __syncthreads();

        if (tid < BQ) {
            float ts = 0.0f;
            #pragma unroll
            for (int k = 0; k < 16; ++k) ts += red[tid * RDP + k];
            l_s[tid] = l_s[tid] * __expf(mo - mn) + ts;
            m_s[tid] = mn;
        }
        __syncthreads();
    }

    if (tid < BQ) li_s[tid] = 1.0f / l_s[tid];
    __syncthreads();

    // ---------------- PASS 2: reload S, threshold, P @ V ----------------
    float o[4][8];
    #pragma unroll
    for (int i = 0; i < 4; ++i)
        #pragma unroll
        for (int j = 0; j < 8; ++j) o[i][j] = 0.0f;

    for (int kt = 0; kt <= qt; ++kt) {
        const int s0 = kt * BKT;
        for (int e = tid; e < BKT * DD; e += 256) {
            int r = e >> 7, d = e & 127;
            Vs[r * QP + d] = Vb[(size_t)(s0 + r) * KVC + d];
        }
        __syncthreads();

        #pragma unroll
        for (int i = 0; i < 4; ++i) {
            const int r = ty + 16 * i;
            const float mr = m_s[r];
            const float li = li_s[r];
            #pragma unroll
            for (int j = 0; j < 4; ++j) {
                const int c = tx + 16 * j;
                float s = Sb[(size_t)r * TT + s0 + c];
                float p = __expf(s - mr) * li;
                if (p < thr) p = 0.0f;
                Ps[r * PP + c] = p;
            }
        }
        __syncthreads();

        for (int s = 0; s < BKT; ++s) {
            float pv[4], vv[8];
            #pragma unroll
            for (int i = 0; i < 4; ++i) pv[i] = Ps[(ty + 16 * i) * PP + s];
            #pragma unroll
            for (int j = 0; j < 8; ++j) vv[j] = Vs[s * QP + tx + 16 * j];
            #pragma unroll
            for (int i = 0; i < 4; ++i)
                #pragma unroll
                for (int j = 0; j < 8; ++j)
                    o[i][j] = fmaf(pv[i], vv[j], o[i][j]);
        }
        __syncthreads();
    }

    #pragma unroll
    for (int i = 0; i < 4; ++i) {
        const int r = ty + 16 * i;
        #pragma unroll
        for (int j = 0; j < 8; ++j) {
            const int c = tx + 16 * j;
            Y[(size_t)(b * TT + q0 + r) * CC + h * DD + c] = o[i][j];
        }
    }
}

// ---------------------------------------------------------------------------
// Launch
// ---------------------------------------------------------------------------
extern "C" void kernel_launch(void* const* d_in, const int* in_sizes, int n_in,
                              void* d_out, int out_size)
{
    const float* x    = (const float*)d_in[0];
    const float* cosb = (const float*)d_in[1];
    const float* sinb = (const float*)d_in[2];
    const float* Wq   = (const float*)d_in[3];
    const float* Wk   = (const float*)d_in[4];
    const float* Wv   = (const float*)d_in[5];
    const float* Wo   = (const float*)d_in[6];
    const float* gate = (const float*)d_in[7];
    float* out = (float*)d_out;

    float *q, *k, *v, *y;
    cudaGetSymbolAddress((void**)&q, g_q);
    cudaGetSymbolAddress((void**)&k, g_k);
    cudaGetSymbolAddress((void**)&v, g_v);
    cudaGetSymbolAddress((void**)&y, g_y);

    // Projections: q/k feed the discontinuous gate -> tf32x3; v is smooth -> tf32
    tgemm_kernel<3><<<dim3(CC / 128, MROWS / 128), 256>>>(MROWS, CC,  CC, x, Wq, q);
    tgemm_kernel<3><<<dim3(KVC / 128, MROWS / 128), 256>>>(MROWS, KVC, CC, x, Wk, k);
    tgemm_kernel<1><<<dim3(KVC / 128, MROWS / 128), 256>>>(MROWS, KVC, CC, x, Wv, v);

    // RoPE (in place)
    {
        int totq = BB * TT * HH   * (RR / 2);
        int totk = BB * TT * HKVV * (RR / 2);
        rope_kernel<<<(totq + 255) / 256, 256>>>(q, cosb, sinb, HH,   CC,  totq);
        rope_kernel<<<(totk + 255) / 256, 256>>>(k, cosb, sinb, HKVV, KVC, totk);
    }

    // Attention (S stashed to global between passes)
    static bool attr_set = false;
    if (!attr_set) {
        cudaFuncSetAttribute(attn_kernel,
                             cudaFuncAttributeMaxDynamicSharedMemorySize,
                             ATT_SMEM_BYTES);
        attr_set = true;
    }
    attn_kernel<<<dim3(TT / BQ, BB * HH), 256, ATT_SMEM_BYTES>>>(q, k, v, gate, y);

    // Output projection (smooth path -> single tf32)
    tgemm_kernel<1><<<dim3(CC / 128, MROWS / 128), 256>>>(MROWS, CC, CC, y, Wo, out);
}

// round 8
// speedup vs baseline: 1.7205x; 1.1178x over previous
#include <cuda_runtime.h>
#include <cuda_bf16.h>
#include <cstdint>
#include <stdint.h>
#include <math.h>

// Problem constants
constexpr int BB  = 2;
constexpr int TT  = 2048;
constexpr int CC  = 2048;
constexpr int HH  = 16;
constexpr int HKVV = 4;
constexpr int DD  = 128;
constexpr int RR  = 64;
constexpr int KVC = HKVV * DD;      // 512
constexpr int REP = HH / HKVV;      // 4
constexpr int MROWS = BB * TT;      // 4096

// ---------------------------------------------------------------------------
// Scratch (static __device__ arrays; no allocations allowed)
// ---------------------------------------------------------------------------
__device__ float g_q[(size_t)MROWS * CC];            // 33.5 MB
__device__ float g_k[(size_t)MROWS * KVC];           //  8.4 MB
__device__ float g_v[(size_t)MROWS * KVC];           //  8.4 MB
__device__ float g_y[(size_t)MROWS * CC];            // 33.5 MB
__device__ float g_s[(size_t)BB * HH * TT * TT];     // 537 MB — e = exp(s - mn_kt) stash

// ---------------------------------------------------------------------------
// tf32 helpers
// ---------------------------------------------------------------------------
__device__ __forceinline__ unsigned int f2tf(float f) {
    unsigned int r;
    asm("cvt.rna.tf32.f32 %0, %1;" : "=r"(r) : "f"(f));
    return r;
}

__device__ __forceinline__ void split_tf32(float f, unsigned int& hi, unsigned int& lo) {
    asm("cvt.rna.tf32.f32 %0, %1;" : "=r"(hi) : "f"(f));
    float hif = __uint_as_float(hi);
    float lof = f - hif;
    asm("cvt.rna.tf32.f32 %0, %1;" : "=r"(lo) : "f"(lof));
}

__device__ __forceinline__ void cp16(void* smem_ptr, const void* gptr) {
    unsigned int s = (unsigned int)__cvta_generic_to_shared(smem_ptr);
    asm volatile("cp.async.cg.shared.global [%0], [%1], 16;" :: "r"(s), "l"(gptr));
}

__device__ __forceinline__ void mma_tf32(float* d, const unsigned int* a, const unsigned int* b) {
    asm volatile(
        "mma.sync.aligned.m16n8k8.row.col.f32.tf32.tf32.f32 "
        "{%0,%1,%2,%3}, {%4,%5,%6,%7}, {%8,%9}, {%0,%1,%2,%3};"
        : "+f"(d[0]), "+f"(d[1]), "+f"(d[2]), "+f"(d[3])
        : "r"(a[0]), "r"(a[1]), "r"(a[2]), "r"(a[3]), "r"(b[0]), "r"(b[1]));
}

// ---------------------------------------------------------------------------
// tf32 tensor-core GEMM, templated on SPLIT (3 = tf32x3, 1 = single tf32).
// Block tile 128x128x16, 8 warps (2x4), warp tile 64x32, m16n8k8 MMA.
// ---------------------------------------------------------------------------
template <int SPLIT>
__global__ __launch_bounds__(256) void tgemm_kernel(
    int M, int N, int K,
    const float* __restrict__ A, const float* __restrict__ B,
    float* __restrict__ C)
{
    constexpr int BM = 128, BN = 128, BK = 16, AP = 20, BP = 136;
    __shared__ float As[2][BM * AP];
    __shared__ float Bs[2][BK * BP];

    const int tid  = threadIdx.x;
    const int lane = tid & 31;
    const int w    = tid >> 5;
    const int wm   = w >> 2;
    const int wn   = w & 3;
    const int grp  = lane >> 2;
    const int qid  = lane & 3;

    const size_t bm = (size_t)blockIdx.y * BM;
    const size_t bn = (size_t)blockIdx.x * BN;

    float acc[4][4][4];
    #pragma unroll
    for (int i = 0; i < 4; ++i)
        #pragma unroll
        for (int j = 0; j < 4; ++j)
            #pragma unroll
            for (int c = 0; c < 4; ++c) acc[i][j][c] = 0.0f;

    auto load_stage = [&](int k0, int buf) {
        #pragma unroll
        for (int c = 0; c < 2; ++c) {
            int idx = tid + c * 256;
            int row = idx >> 2, col = (idx & 3) * 4;
            cp16(&As[buf][row * AP + col], &A[(bm + row) * (size_t)K + k0 + col]);
        }
        #pragma unroll
        for (int c = 0; c < 2; ++c) {
            int idx = tid + c * 256;
            int row = idx >> 5, col = (idx & 31) * 4;
            cp16(&Bs[buf][row * BP + col], &B[(size_t)(k0 + row) * N + bn + col]);
        }
    };

    load_stage(0, 0);
    asm volatile("cp.async.commit_group;");

    const int nst = K / BK;
    for (int s = 0; s < nst; ++s) {
        asm volatile("cp.async.wait_group 0;");
        __syncthreads();
        const int cur = s & 1;
        if (s + 1 < nst) {
            load_stage((s + 1) * BK, cur ^ 1);
            asm volatile("cp.async.commit_group;");
        }

        const float* Asb = As[cur];
        const float* Bsb = Bs[cur];
        #pragma unroll
        for (int ks = 0; ks < BK; ks += 8) {
            unsigned int afh[4][4], afl[4][4], bfh[4][2], bfl[4][2];
            #pragma unroll
            for (int mt = 0; mt < 4; ++mt) {
                int r0 = wm * 64 + mt * 16 + grp;
                if (SPLIT == 3) {
                    split_tf32(Asb[r0 * AP + ks + qid],           afh[mt][0], afl[mt][0]);
                    split_tf32(Asb[(r0 + 8) * AP + ks + qid],     afh[mt][1], afl[mt][1]);
                    split_tf32(Asb[r0 * AP + ks + qid + 4],       afh[mt][2], afl[mt][2]);
                    split_tf32(Asb[(r0 + 8) * AP + ks + qid + 4], afh[mt][3], afl[mt][3]);
                } else {
                    afh[mt][0] = f2tf(Asb[r0 * AP + ks + qid]);
                    afh[mt][1] = f2tf(Asb[(r0 + 8) * AP + ks + qid]);
                    afh[mt][2] = f2tf(Asb[r0 * AP + ks + qid + 4]);
                    afh[mt][3] = f2tf(Asb[(r0 + 8) * AP + ks + qid + 4]);
                }
            }
            #pragma unroll
            for (int nt = 0; nt < 4; ++nt) {
                int c0 = wn * 32 + nt * 8 + grp;
                if (SPLIT == 3) {
                    split_tf32(Bsb[(ks + qid) * BP + c0],     bfh[nt][0], bfl[nt][0]);
                    split_tf32(Bsb[(ks + qid + 4) * BP + c0], bfh[nt][1], bfl[nt][1]);
                } else {
                    bfh[nt][0] = f2tf(Bsb[(ks + qid) * BP + c0]);
                    bfh[nt][1] = f2tf(Bsb[(ks + qid + 4) * BP + c0]);
                }
            }
            #pragma unroll
            for (int mt = 0; mt < 4; ++mt)
                #pragma unroll
                for (int nt = 0; nt < 4; ++nt) {
                    if (SPLIT == 3) {
                        mma_tf32(acc[mt][nt], afl[mt], bfh[nt]);
                        mma_tf32(acc[mt][nt], afh[mt], bfl[nt]);
                    }
                    mma_tf32(acc[mt][nt], afh[mt], bfh[nt]);
                }
        }
        __syncthreads();
    }

    #pragma unroll
    for (int mt = 0; mt < 4; ++mt) {
        #pragma unroll
        for (int nt = 0; nt < 4; ++nt) {
            size_t r  = bm + wm * 64 + mt * 16 + grp;
            size_t c0 = bn + wn * 32 + nt * 8 + 2 * qid;
            *(float2*)&C[r * (size_t)N + c0]       = make_float2(acc[mt][nt][0], acc[mt][nt][1]);
            *(float2*)&C[(r + 8) * (size_t)N + c0] = make_float2(acc[mt][nt][2], acc[mt][nt][3]);
        }
    }
}

// ---------------------------------------------------------------------------
// RoPE (in place)
// ---------------------------------------------------------------------------
__global__ void rope_kernel(float* __restrict__ buf,
                            const float* __restrict__ cosb,
                            const float* __restrict__ sinb,
                            int nh, int pitch, int total)
{
    int idx = blockIdx.x * blockDim.x + threadIdx.x;
    if (idx >= total) return;
    constexpr int RH = RR / 2;
    int r   = idx % RH;
    int h   = (idx / RH) % nh;
    int row = idx / (RH * nh);
    int t   = row % TT;

    float* p = buf + (size_t)row * pitch + h * DD;
    float c1 = cosb[t * RR + r],       s1 = sinb[t * RR + r];
    float c2 = cosb[t * RR + r + RH],  s2 = sinb[t * RR + r + RH];
    float x1 = p[r], x2 = p[r + RH];
    p[r]      = x1 * c1 - x2 * s1;
    p[r + RH] = x2 * c2 + x1 * s2;
}

// ---------------------------------------------------------------------------
// Two-pass causal attention with threshold gating.
// Pass 1: QK (SIMT fp32, gate-critical), stash e=exp(s-mn_kt) + mn_kt; online m,l.
// Pass 2: p = e * corr(r,kt) (one exp per row-tile), gate, PV via tf32 MMA.
// ---------------------------------------------------------------------------
constexpr int BQ  = 64;
constexpr int BKT = 64;
constexpr int QP  = 129;   // Qs/Ks pitch
constexpr int VPITCH = 136;  // Vs (tf32 bits), conflict-free B-fragments
constexpr int PPITCH = 68;   // Ps (tf32 bits), conflict-free A-fragments
constexpr int RDP = 17;
constexpr int NKT = TT / BKT;  // 32
constexpr int ATT_SMEM_FLOATS =
    2 * BQ * QP + BQ * VPITCH + BQ * PPITCH + BQ * RDP + NKT * BQ + 4 * BQ;
constexpr int ATT_SMEM_BYTES = ATT_SMEM_FLOATS * 4;   // 131840

__global__ __launch_bounds__(256, 1) void attn_kernel(
    const float* __restrict__ Q, const float* __restrict__ Km,
    const float* __restrict__ Vm, const float* __restrict__ gate,
    float* __restrict__ Y)
{
    extern __shared__ float sm[];
    float* Qs     = sm;                         // [64][129]
    float* Ks     = Qs + BQ * QP;               // [64][129]
    float* Vs     = Ks + BQ * QP;               // [64][136] tf32 bits
    float* Ps     = Vs + BQ * VPITCH;           // [64][68]  tf32 bits
    float* red    = Ps + BQ * PPITCH;           // [64][17]
    float* mn_all = red + BQ * RDP;             // [32][64]
    float* m_s    = mn_all + NKT * BQ;          // [64]
    float* l_s    = m_s + BQ;
    float* mn_s   = l_s + BQ;                   // reused as corr_s in pass 2
    float* li_s   = mn_s + BQ;
    unsigned int* Vsu = (unsigned int*)Vs;
    unsigned int* Psu = (unsigned int*)Ps;

    const int qt = blockIdx.x;
    const int bh = blockIdx.y;
    const int b  = bh / HH;
    const int h  = bh % HH;
    const int q0 = qt * BQ;
    const int tid  = threadIdx.x;
    const int ty   = tid / 16;
    const int tx   = tid % 16;
    const int lane = tid & 31;
    const int w    = tid >> 5;
    const int wm   = w >> 2;            // 0..1
    const int wn   = w & 3;             // 0..3
    const int grp  = lane >> 2;         // 0..7
    const int qid  = lane & 3;          // 0..3

    const float scale = 0.08838834764831845f;
    const float thr = 1.0f / (1.0f + __expf(-gate[h]));

    const float* Qb = Q  + (size_t)(b * TT) * CC  + h * DD;
    const float* Kb = Km + (size_t)(b * TT) * KVC + (h / REP) * DD;
    const float* Vb = Vm + (size_t)(b * TT) * KVC + (h / REP) * DD;
    float* Eb = g_s + ((size_t)bh * TT + q0) * TT;   // e-stash rows q0..q0+63

    for (int e = tid; e < BQ * DD; e += 256) {
        int r = e >> 7, d = e & 127;
        Qs[r * QP + d] = Qb[(size_t)(q0 + r) * CC + d];
    }
    if (tid < BQ) { m_s[tid] = -1e30f; l_s[tid] = 0.0f; }
    __syncthreads();

    // ---------------- PASS 1: QK (SIMT), stash e + mn, online m,l ----------------
    for (int kt = 0; kt <= qt; ++kt) {
        const int s0 = kt * BKT;
        for (int e = tid; e < BKT * DD; e += 256) {
            int r = e >> 7, d = e & 127;
            Ks[r * QP + d] = Kb[(size_t)(s0 + r) * KVC + d];
        }
        __syncthreads();

        float acc[4][4];
        #pragma unroll
        for (int i = 0; i < 4; ++i)
            #pragma unroll
            for (int j = 0; j < 4; ++j) acc[i][j] = 0.0f;

        for (int d = 0; d < DD; ++d) {
            float a[4], bb[4];
            #pragma unroll
            for (int i = 0; i < 4; ++i) a[i]  = Qs[(ty + 16 * i) * QP + d];
            #pragma unroll
            for (int j = 0; j < 4; ++j) bb[j] = Ks[(tx + 16 * j) * QP + d];
            #pragma unroll
            for (int i = 0; i < 4; ++i)
                #pragma unroll
                for (int j = 0; j < 4; ++j)
                    acc[i][j] = fmaf(a[i], bb[j], acc[i][j]);
        }
        #pragma unroll
        for (int i = 0; i < 4; ++i) {
            const int r = ty + 16 * i;
            float pm = -1e30f;
            #pragma unroll
            for (int j = 0; j < 4; ++j) {
                const int c = tx + 16 * j;
                float s = acc[i][j] * scale;
                if (kt == qt && c > r) s = -1e30f;
                acc[i][j] = s;
                pm = fmaxf(pm, s);
            }
            red[r * RDP + tx] = pm;
        }
        __syncthreads();

        float mo = 0.0f, mn = 0.0f;
        if (tid < BQ) {
            float tm = red[tid * RDP];
            #pragma unroll
            for (int k = 1; k < 16; ++k) tm = fmaxf(tm, red[tid * RDP + k]);
            mo = m_s[tid];
            mn = fmaxf(mo, tm);
            mn_s[tid] = mn;
            mn_all[kt * BQ + tid] = mn;
        }
        __syncthreads();

        // e = exp(s - mn_kt): stash + partial row sums
        #pragma unroll
        for (int i = 0; i < 4; ++i) {
            const int r = ty + 16 * i;
            const float mr = mn_s[r];
            float ps = 0.0f;
            #pragma unroll
            for (int j = 0; j < 4; ++j) {
                const int c = tx + 16 * j;
                float ei = __expf(acc[i][j] - mr);
                Eb[(size_t)r * TT + s0 + c] = ei;
                ps += ei;
            }
            red[r * RDP + tx] = ps;
        }
        __syncthreads();

        if (tid < BQ) {
            float ts = 0.0f;
            #pragma unroll
            for (int k = 0; k < 16; ++k) ts += red[tid * RDP + k];
            l_s[tid] = l_s[tid] * __expf(mo - mn) + ts;
            m_s[tid] = mn;
        }
        __syncthreads();
    }

    if (tid < BQ) li_s[tid] = 1.0f / l_s[tid];
    __syncthreads();

    // ---------------- PASS 2: gate + PV via tf32 MMA ----------------
    float o[2][4][4];
    #pragma unroll
    for (int mt = 0; mt < 2; ++mt)
        #pragma unroll
        for (int nt = 0; nt < 4; ++nt)
            #pragma unroll
            for (int c = 0; c < 4; ++c) o[mt][nt][c] = 0.0f;

    const int m0 = wm * 32;
    const int n0 = wn * 32;

    for (int kt = 0; kt <= qt; ++kt) {
        const int s0 = kt * BKT;

        // V tile -> smem as tf32 bits
        for (int e = tid; e < BKT * DD; e += 256) {
            int r = e >> 7, d = e & 127;
            Vsu[r * VPITCH + d] = f2tf(Vb[(size_t)(s0 + r) * KVC + d]);
        }
        // per-row correction: corr = exp(mn_kt - m) * (1/l)
        if (tid < BQ)
            mn_s[tid] = __expf(mn_all[kt * BQ + tid] - m_s[tid]) * li_s[tid];
        __syncthreads();

        // P tile: p = e * corr, gate, -> tf32 bits
        for (int e = tid; e < BQ * BKT; e += 256) {
            int r = e >> 6, c = e & 63;
            float p = Eb[(size_t)r * TT + s0 + c] * mn_s[r];
            if (p < thr) p = 0.0f;
            Psu[r * PPITCH + c] = f2tf(p);
        }
        __syncthreads();

        // PV MMA: warp tile 32m x 32n, k = 64
        #pragma unroll
        for (int k = 0; k < BKT; k += 8) {
            unsigned int af[2][4], bf[4][2];
            #pragma unroll
            for (int mt = 0; mt < 2; ++mt) {
                int rr = m0 + mt * 16 + grp;
                af[mt][0] = Psu[rr * PPITCH + k + qid];
                af[mt][1] = Psu[(rr + 8) * PPITCH + k + qid];
                af[mt][2] = Psu[rr * PPITCH + k + qid + 4];
                af[mt][3] = Psu[(rr + 8) * PPITCH + k + qid + 4];
            }
            #pragma unroll
            for (int nt = 0; nt < 4; ++nt) {
                int cc = n0 + nt * 8 + grp;
                bf[nt][0] = Vsu[(k + qid) * VPITCH + cc];
                bf[nt][1] = Vsu[(k + qid + 4) * VPITCH + cc];
            }
            #pragma unroll
            for (int mt = 0; mt < 2; ++mt)
                #pragma unroll
                for (int nt = 0; nt < 4; ++nt)
                    mma_tf32(o[mt][nt], af[mt], bf[nt]);
        }
        __syncthreads();
    }

    // Write Y (fragment epilogue)
    #pragma unroll
    for (int mt = 0; mt < 2; ++mt) {
        #pragma unroll
        for (int nt = 0; nt < 4; ++nt) {
            size_t row = (size_t)(b * TT + q0 + m0 + mt * 16 + grp);
            size_t col = h * DD + n0 + nt * 8 + 2 * qid;
            *(float2*)&Y[row * CC + col]       = make_float2(o[mt][nt][0], o[mt][nt][1]);
            *(float2*)&Y[(row + 8) * CC + col] = make_float2(o[mt][nt][2], o[mt][nt][3]);
        }
    }
}

// ---------------------------------------------------------------------------
// Launch
// ---------------------------------------------------------------------------
extern "C" void kernel_launch(void* const* d_in, const int* in_sizes, int n_in,
                              void* d_out, int out_size)
{
    const float* x    = (const float*)d_in[0];
    const float* cosb = (const float*)d_in[1];
    const float* sinb = (const float*)d_in[2];
    const float* Wq   = (const float*)d_in[3];
    const float* Wk   = (const float*)d_in[4];
    const float* Wv   = (const float*)d_in[5];
    const float* Wo   = (const float*)d_in[6];
    const float* gate = (const float*)d_in[7];
    float* out = (float*)d_out;

    float *q, *k, *v, *y;
    cudaGetSymbolAddress((void**)&q, g_q);
    cudaGetSymbolAddress((void**)&k, g_k);
    cudaGetSymbolAddress((void**)&v, g_v);
    cudaGetSymbolAddress((void**)&y, g_y);

    // Projections: q/k feed the discontinuous gate -> tf32x3; v is smooth -> tf32
    tgemm_kernel<3><<<dim3(CC / 128, MROWS / 128), 256>>>(MROWS, CC,  CC, x, Wq, q);
    tgemm_kernel<3><<<dim3(KVC / 128, MROWS / 128), 256>>>(MROWS, KVC, CC, x, Wk, k);
    tgemm_kernel<1><<<dim3(KVC / 128, MROWS / 128), 256>>>(MROWS, KVC, CC, x, Wv, v);

    // RoPE (in place)
    {
        int totq = BB * TT * HH   * (RR / 2);
        int totk = BB * TT * HKVV * (RR / 2);
        rope_kernel<<<(totq + 255) / 256, 256>>>(q, cosb, sinb, HH,   CC,  totq);
        rope_kernel<<<(totk + 255) / 256, 256>>>(k, cosb, sinb, HKVV, KVC, totk);
    }

    // Attention
    static bool attr_set = false;
    if (!attr_set) {
        cudaFuncSetAttribute(attn_kernel,
                             cudaFuncAttributeMaxDynamicSharedMemorySize,
                             ATT_SMEM_BYTES);
        attr_set = true;
    }
    attn_kernel<<<dim3(TT / BQ, BB * HH), 256, ATT_SMEM_BYTES>>>(q, k, v, gate, y);

    // Output projection (smooth path -> single tf32)
    tgemm_kernel<1><<<dim3(CC / 128, MROWS / 128), 256>>>(MROWS, CC, CC, y, Wo, out);
}

// round 9
// speedup vs baseline: 1.9115x; 1.1110x over previous
#include <cuda_runtime.h>
#include <cuda_bf16.h>
#include <cstdint>
#include <stdint.h>
#include <math.h>

// Problem constants
constexpr int BB  = 2;
constexpr int TT  = 2048;
constexpr int CC  = 2048;
constexpr int HH  = 16;
constexpr int HKVV = 4;
constexpr int DD  = 128;
constexpr int RR  = 64;
constexpr int KVC = HKVV * DD;      // 512
constexpr int REP = HH / HKVV;      // 4
constexpr int MROWS = BB * TT;      // 4096

// ---------------------------------------------------------------------------
// Scratch (static __device__ arrays; no allocations allowed)
// ---------------------------------------------------------------------------
__device__ float g_q[(size_t)MROWS * CC];            // 33.5 MB
__device__ float g_k[(size_t)MROWS * KVC];           //  8.4 MB
__device__ float g_v[(size_t)MROWS * KVC];           //  8.4 MB
__device__ float g_y[(size_t)MROWS * CC];            // 33.5 MB
__device__ float g_s[(size_t)BB * HH * TT * TT];     // 537 MB — e = exp(s - mn_kt) stash

// ---------------------------------------------------------------------------
// precision helpers
// ---------------------------------------------------------------------------
__device__ __forceinline__ unsigned int f2tf(float f) {
    unsigned int r;
    asm("cvt.rna.tf32.f32 %0, %1;" : "=r"(r) : "f"(f));
    return r;
}

// bf16x2 split of a float pair: hi = bf16(f), lo = bf16(f - hi), packed (f0 low, f1 high)
__device__ __forceinline__ void split_bf16x2(float f0, float f1,
                                             unsigned int& hi, unsigned int& lo) {
    __nv_bfloat162 h = __floats2bfloat162_rn(f0, f1);
    float2 hf = __bfloat1622float2(h);
    __nv_bfloat162 l = __floats2bfloat162_rn(f0 - hf.x, f1 - hf.y);
    hi = *reinterpret_cast<unsigned int*>(&h);
    lo = *reinterpret_cast<unsigned int*>(&l);
}

__device__ __forceinline__ void cp16(void* smem_ptr, const void* gptr) {
    unsigned int s = (unsigned int)__cvta_generic_to_shared(smem_ptr);
    asm volatile("cp.async.cg.shared.global [%0], [%1], 16;" :: "r"(s), "l"(gptr));
}

__device__ __forceinline__ void mma_tf32(float* d, const unsigned int* a, const unsigned int* b) {
    asm volatile(
        "mma.sync.aligned.m16n8k8.row.col.f32.tf32.tf32.f32 "
        "{%0,%1,%2,%3}, {%4,%5,%6,%7}, {%8,%9}, {%0,%1,%2,%3};"
        : "+f"(d[0]), "+f"(d[1]), "+f"(d[2]), "+f"(d[3])
        : "r"(a[0]), "r"(a[1]), "r"(a[2]), "r"(a[3]), "r"(b[0]), "r"(b[1]));
}

__device__ __forceinline__ void mma_bf16(float* d, const unsigned int* a, const unsigned int* b) {
    asm volatile(
        "mma.sync.aligned.m16n8k16.row.col.f32.bf16.bf16.f32 "
        "{%0,%1,%2,%3}, {%4,%5,%6,%7}, {%8,%9}, {%0,%1,%2,%3};"
        : "+f"(d[0]), "+f"(d[1]), "+f"(d[2]), "+f"(d[3])
        : "r"(a[0]), "r"(a[1]), "r"(a[2]), "r"(a[3]), "r"(b[0]), "r"(b[1]));
}

// ---------------------------------------------------------------------------
// Tensor-core GEMM, templated on PREC:
//   PREC=3 -> bf16x2 3-term (hi*hi + lo*hi + hi*lo via m16n8k16, ~4e-6 rel err)
//   PREC=1 -> single tf32 m16n8k8 (~3e-4 rel err — smooth paths only)
// Block tile 128x128x16, 8 warps (2x4), warp tile 64x32.
// cp.async double-buffered smem. A pitch 20, B pitch 136.
// ---------------------------------------------------------------------------
template <int PREC>
__global__ __launch_bounds__(256) void tgemm_kernel(
    int M, int N, int K,
    const float* __restrict__ A, const float* __restrict__ B,
    float* __restrict__ C)
{
    constexpr int BM = 128, BN = 128, BK = 16, AP = 20, BP = 136;
    __shared__ float As[2][BM * AP];
    __shared__ float Bs[2][BK * BP];

    const int tid  = threadIdx.x;
    const int lane = tid & 31;
    const int w    = tid >> 5;
    const int wm   = w >> 2;
    const int wn   = w & 3;
    const int grp  = lane >> 2;
    const int qid  = lane & 3;

    const size_t bm = (size_t)blockIdx.y * BM;
    const size_t bn = (size_t)blockIdx.x * BN;

    float acc[4][4][4];
    #pragma unroll
    for (int i = 0; i < 4; ++i)
        #pragma unroll
        for (int j = 0; j < 4; ++j)
            #pragma unroll
            for (int c = 0; c < 4; ++c) acc[i][j][c] = 0.0f;

    auto load_stage = [&](int k0, int buf) {
        #pragma unroll
        for (int c = 0; c < 2; ++c) {
            int idx = tid + c * 256;
            int row = idx >> 2, col = (idx & 3) * 4;
            cp16(&As[buf][row * AP + col], &A[(bm + row) * (size_t)K + k0 + col]);
        }
        #pragma unroll
        for (int c = 0; c < 2; ++c) {
            int idx = tid + c * 256;
            int row = idx >> 5, col = (idx & 31) * 4;
            cp16(&Bs[buf][row * BP + col], &B[(size_t)(k0 + row) * N + bn + col]);
        }
    };

    load_stage(0, 0);
    asm volatile("cp.async.commit_group;");

    const int nst = K / BK;
    for (int s = 0; s < nst; ++s) {
        asm volatile("cp.async.wait_group 0;");
        __syncthreads();
        const int cur = s & 1;
        if (s + 1 < nst) {
            load_stage((s + 1) * BK, cur ^ 1);
            asm volatile("cp.async.commit_group;");
        }

        const float* Asb = As[cur];
        const float* Bsb = Bs[cur];

        if (PREC == 3) {
            // bf16x2 3-term, one m16n8k16 step covers BK=16
            unsigned int ah[4][4], al[4][4], bh[4][2], bl[4][2];
            #pragma unroll
            for (int mt = 0; mt < 4; ++mt) {
                int r0 = wm * 64 + mt * 16 + grp;
                int c0 = 2 * qid;
                split_bf16x2(Asb[r0 * AP + c0],           Asb[r0 * AP + c0 + 1],
                             ah[mt][0], al[mt][0]);
                split_bf16x2(Asb[(r0 + 8) * AP + c0],     Asb[(r0 + 8) * AP + c0 + 1],
                             ah[mt][1], al[mt][1]);
                split_bf16x2(Asb[r0 * AP + c0 + 8],       Asb[r0 * AP + c0 + 9],
                             ah[mt][2], al[mt][2]);
                split_bf16x2(Asb[(r0 + 8) * AP + c0 + 8], Asb[(r0 + 8) * AP + c0 + 9],
                             ah[mt][3], al[mt][3]);
            }
            #pragma unroll
            for (int nt = 0; nt < 4; ++nt) {
                int c0 = wn * 32 + nt * 8 + grp;
                int k0 = 2 * qid;
                split_bf16x2(Bsb[k0 * BP + c0],       Bsb[(k0 + 1) * BP + c0],
                             bh[nt][0], bl[nt][0]);
                split_bf16x2(Bsb[(k0 + 8) * BP + c0], Bsb[(k0 + 9) * BP + c0],
                             bh[nt][1], bl[nt][1]);
            }
            #pragma unroll
            for (int mt = 0; mt < 4; ++mt)
                #pragma unroll
                for (int nt = 0; nt < 4; ++nt) {
                    mma_bf16(acc[mt][nt], al[mt], bh[nt]);   // lo*hi
                    mma_bf16(acc[mt][nt], ah[mt], bl[nt]);   // hi*lo
                    mma_bf16(acc[mt][nt], ah[mt], bh[nt]);   // hi*hi
                }
        } else {
            // single tf32, two m16n8k8 steps
            #pragma unroll
            for (int ks = 0; ks < BK; ks += 8) {
                unsigned int af[4][4], bf[4][2];
                #pragma unroll
                for (int mt = 0; mt < 4; ++mt) {
                    int r0 = wm * 64 + mt * 16 + grp;
                    af[mt][0] = f2tf(Asb[r0 * AP + ks + qid]);
                    af[mt][1] = f2tf(Asb[(r0 + 8) * AP + ks + qid]);
                    af[mt][2] = f2tf(Asb[r0 * AP + ks + qid + 4]);
                    af[mt][3] = f2tf(Asb[(r0 + 8) * AP + ks + qid + 4]);
                }
                #pragma unroll
                for (int nt = 0; nt < 4; ++nt) {
                    int c0 = wn * 32 + nt * 8 + grp;
                    bf[nt][0] = f2tf(Bsb[(ks + qid) * BP + c0]);
                    bf[nt][1] = f2tf(Bsb[(ks + qid + 4) * BP + c0]);
                }
                #pragma unroll
                for (int mt = 0; mt < 4; ++mt)
                    #pragma unroll
                    for (int nt = 0; nt < 4; ++nt)
                        mma_tf32(acc[mt][nt], af[mt], bf[nt]);
            }
        }
        __syncthreads();
    }

    #pragma unroll
    for (int mt = 0; mt < 4; ++mt) {
        #pragma unroll
        for (int nt = 0; nt < 4; ++nt) {
            size_t r  = bm + wm * 64 + mt * 16 + grp;
            size_t c0 = bn + wn * 32 + nt * 8 + 2 * qid;
            *(float2*)&C[r * (size_t)N + c0]       = make_float2(acc[mt][nt][0], acc[mt][nt][1]);
            *(float2*)&C[(r + 8) * (size_t)N + c0] = make_float2(acc[mt][nt][2], acc[mt][nt][3]);
        }
    }
}

// ---------------------------------------------------------------------------
// RoPE (in place)
// ---------------------------------------------------------------------------
__global__ void rope_kernel(float* __restrict__ buf,
                            const float* __restrict__ cosb,
                            const float* __restrict__ sinb,
                            int nh, int pitch, int total)
{
    int idx = blockIdx.x * blockDim.x + threadIdx.x;
    if (idx >= total) return;
    constexpr int RH = RR / 2;
    int r   = idx % RH;
    int h   = (idx / RH) % nh;
    int row = idx / (RH * nh);
    int t   = row % TT;

    float* p = buf + (size_t)row * pitch + h * DD;
    float c1 = cosb[t * RR + r],       s1 = sinb[t * RR + r];
    float c2 = cosb[t * RR + r + RH],  s2 = sinb[t * RR + r + RH];
    float x1 = p[r], x2 = p[r + RH];
    p[r]      = x1 * c1 - x2 * s1;
    p[r + RH] = x2 * c2 + x1 * s2;
}

// ---------------------------------------------------------------------------
// Two-pass causal attention with threshold gating (unchanged from R8).
// ---------------------------------------------------------------------------
constexpr int BQ  = 64;
constexpr int BKT = 64;
constexpr int QP  = 129;
constexpr int VPITCH = 136;
constexpr int PPITCH = 68;
constexpr int RDP = 17;
constexpr int NKT = TT / BKT;
constexpr int ATT_SMEM_FLOATS =
    2 * BQ * QP + BQ * VPITCH + BQ * PPITCH + BQ * RDP + NKT * BQ + 4 * BQ;
constexpr int ATT_SMEM_BYTES = ATT_SMEM_FLOATS * 4;   // 131840

__global__ __launch_bounds__(256, 1) void attn_kernel(
    const float* __restrict__ Q, const float* __restrict__ Km,
    const float* __restrict__ Vm, const float* __restrict__ gate,
    float* __restrict__ Y)
{
    extern __shared__ float sm[];
    float* Qs     = sm;
    float* Ks     = Qs + BQ * QP;
    float* Vs     = Ks + BQ * QP;
    float* Ps     = Vs + BQ * VPITCH;
    float* red    = Ps + BQ * PPITCH;
    float* mn_all = red + BQ * RDP;
    float* m_s    = mn_all + NKT * BQ;
    float* l_s    = m_s + BQ;
    float* mn_s   = l_s + BQ;
    float* li_s   = mn_s + BQ;
    unsigned int* Vsu = (unsigned int*)Vs;
    unsigned int* Psu = (unsigned int*)Ps;

    const int qt = blockIdx.x;
    const int bh = blockIdx.y;
    const int b  = bh / HH;
    const int h  = bh % HH;
    const int q0 = qt * BQ;
    const int tid  = threadIdx.x;
    const int ty   = tid / 16;
    const int tx   = tid % 16;
    const int lane = tid & 31;
    const int w    = tid >> 5;
    const int wm   = w >> 2;
    const int wn   = w & 3;
    const int grp  = lane >> 2;
    const int qid  = lane & 3;

    const float scale = 0.08838834764831845f;
    const float thr = 1.0f / (1.0f + __expf(-gate[h]));

    const float* Qb = Q  + (size_t)(b * TT) * CC  + h * DD;
    const float* Kb = Km + (size_t)(b * TT) * KVC + (h / REP) * DD;
    const float* Vb = Vm + (size_t)(b * TT) * KVC + (h / REP) * DD;
    float* Eb = g_s + ((size_t)bh * TT + q0) * TT;

    for (int e = tid; e < BQ * DD; e += 256) {
        int r = e >> 7, d = e & 127;
        Qs[r * QP + d] = Qb[(size_t)(q0 + r) * CC + d];
    }
    if (tid < BQ) { m_s[tid] = -1e30f; l_s[tid] = 0.0f; }
    __syncthreads();

    // ---------------- PASS 1: QK (SIMT), stash e + mn, online m,l ----------------
    for (int kt = 0; kt <= qt; ++kt) {
        const int s0 = kt * BKT;
        for (int e = tid; e < BKT * DD; e += 256) {
            int r = e >> 7, d = e & 127;
            Ks[r * QP + d] = Kb[(size_t)(s0 + r) * KVC + d];
        }
        __syncthreads();

        float acc[4][4];
        #pragma unroll
        for (int i = 0; i < 4; ++i)
            #pragma unroll
            for (int j = 0; j < 4; ++j) acc[i][j] = 0.0f;

        for (int d = 0; d < DD; ++d) {
            float a[4], bb[4];
            #pragma unroll
            for (int i = 0; i < 4; ++i) a[i]  = Qs[(ty + 16 * i) * QP + d];
            #pragma unroll
            for (int j = 0; j < 4; ++j) bb[j] = Ks[(tx + 16 * j) * QP + d];
            #pragma unroll
            for (int i = 0; i < 4; ++i)
                #pragma unroll
                for (int j = 0; j < 4; ++j)
                    acc[i][j] = fmaf(a[i], bb[j], acc[i][j]);
        }
        #pragma unroll
        for (int i = 0; i < 4; ++i) {
            const int r = ty + 16 * i;
            float pm = -1e30f;
            #pragma unroll
            for (int j = 0; j < 4; ++j) {
                const int c = tx + 16 * j;
                float s = acc[i][j] * scale;
                if (kt == qt && c > r) s = -1e30f;
                acc[i][j] = s;
                pm = fmaxf(pm, s);
            }
            red[r * RDP + tx] = pm;
        }
        __syncthreads();

        float mo = 0.0f, mn = 0.0f;
        if (tid < BQ) {
            float tm = red[tid * RDP];
            #pragma unroll
            for (int k = 1; k < 16; ++k) tm = fmaxf(tm, red[tid * RDP + k]);
            mo = m_s[tid];
            mn = fmaxf(mo, tm);
            mn_s[tid] = mn;
            mn_all[kt * BQ + tid] = mn;
        }
        __syncthreads();

        #pragma unroll
        for (int i = 0; i < 4; ++i) {
            const int r = ty + 16 * i;
            const float mr = mn_s[r];
            float ps = 0.0f;
            #pragma unroll
            for (int j = 0; j < 4; ++j) {
                const int c = tx + 16 * j;
                float ei = __expf(acc[i][j] - mr);
                Eb[(size_t)r * TT + s0 + c] = ei;
                ps += ei;
            }
            red[r * RDP + tx] = ps;
        }
        __syncthreads();

        if (tid < BQ) {
            float ts = 0.0f;
            #pragma unroll
            for (int k = 0; k < 16; ++k) ts += red[tid * RDP + k];
            l_s[tid] = l_s[tid] * __expf(mo - mn) + ts;
            m_s[tid] = mn;
        }
        __syncthreads();
    }

    if (tid < BQ) li_s[tid] = 1.0f / l_s[tid];
    __syncthreads();

    // ---------------- PASS 2: gate + PV via tf32 MMA ----------------
    float o[2][4][4];
    #pragma unroll
    for (int mt = 0; mt < 2; ++mt)
        #pragma unroll
        for (int nt = 0; nt < 4; ++nt)
            #pragma unroll
            for (int c = 0; c < 4; ++c) o[mt][nt][c] = 0.0f;

    const int m0 = wm * 32;
    const int n0 = wn * 32;

    for (int kt = 0; kt <= qt; ++kt) {
        const int s0 = kt * BKT;

        for (int e = tid; e < BKT * DD; e += 256) {
            int r = e >> 7, d = e & 127;
            Vsu[r * VPITCH + d] = f2tf(Vb[(size_t)(s0 + r) * KVC + d]);
        }
        if (tid < BQ)
            mn_s[tid] = __expf(mn_all[kt * BQ + tid] - m_s[tid]) * li_s[tid];
        __syncthreads();

        for (int e = tid; e < BQ * BKT; e += 256) {
            int r = e >> 6, c = e & 63;
            float p = Eb[(size_t)r * TT + s0 + c] * mn_s[r];
            if (p < thr) p = 0.0f;
            Psu[r * PPITCH + c] = f2tf(p);
        }
        __syncthreads();

        #pragma unroll
        for (int k = 0; k < BKT; k += 8) {
            unsigned int af[2][4], bf[4][2];
            #pragma unroll
            for (int mt = 0; mt < 2; ++mt) {
                int rr = m0 + mt * 16 + grp;
                af[mt][0] = Psu[rr * PPITCH + k + qid];
                af[mt][1] = Psu[(rr + 8) * PPITCH + k + qid];
                af[mt][2] = Psu[rr * PPITCH + k + qid + 4];
                af[mt][3] = Psu[(rr + 8) * PPITCH + k + qid + 4];
            }
            #pragma unroll
            for (int nt = 0; nt < 4; ++nt) {
                int cc = n0 + nt * 8 + grp;
                bf[nt][0] = Vsu[(k + qid) * VPITCH + cc];
                bf[nt][1] = Vsu[(k + qid + 4) * VPITCH + cc];
            }
            #pragma unroll
            for (int mt = 0; mt < 2; ++mt)
                #pragma unroll
                for (int nt = 0; nt < 4; ++nt)
                    mma_tf32(o[mt][nt], af[mt], bf[nt]);
        }
        __syncthreads();
    }

    #pragma unroll
    for (int mt = 0; mt < 2; ++mt) {
        #pragma unroll
        for (int nt = 0; nt < 4; ++nt) {
            size_t row = (size_t)(b * TT + q0 + m0 + mt * 16 + grp);
            size_t col = h * DD + n0 + nt * 8 + 2 * qid;
            *(float2*)&Y[row * CC + col]       = make_float2(o[mt][nt][0], o[mt][nt][1]);
            *(float2*)&Y[(row + 8) * CC + col] = make_float2(o[mt][nt][2], o[mt][nt][3]);
        }
    }
}

// ---------------------------------------------------------------------------
// Launch
// ---------------------------------------------------------------------------
extern "C" void kernel_launch(void* const* d_in, const int* in_sizes, int n_in,
                              void* d_out, int out_size)
{
    const float* x    = (const float*)d_in[0];
    const float* cosb = (const float*)d_in[1];
    const float* sinb = (const float*)d_in[2];
    const float* Wq   = (const float*)d_in[3];
    const float* Wk   = (const float*)d_in[4];
    const float* Wv   = (const float*)d_in[5];
    const float* Wo   = (const float*)d_in[6];
    const float* gate = (const float*)d_in[7];
    float* out = (float*)d_out;

    float *q, *k, *v, *y;
    cudaGetSymbolAddress((void**)&q, g_q);
    cudaGetSymbolAddress((void**)&k, g_k);
    cudaGetSymbolAddress((void**)&v, g_v);
    cudaGetSymbolAddress((void**)&y, g_y);

    // Projections: q/k gate-critical -> bf16x2 3-term; v smooth -> single tf32
    tgemm_kernel<3><<<dim3(CC / 128, MROWS / 128), 256>>>(MROWS, CC,  CC, x, Wq, q);
    tgemm_kernel<3><<<dim3(KVC / 128, MROWS / 128), 256>>>(MROWS, KVC, CC, x, Wk, k);
    tgemm_kernel<1><<<dim3(KVC / 128, MROWS / 128), 256>>>(MROWS, KVC, CC, x, Wv, v);

    // RoPE (in place)
    {
        int totq = BB * TT * HH   * (RR / 2);
        int totk = BB * TT * HKVV * (RR / 2);
        rope_kernel<<<(totq + 255) / 256, 256>>>(q, cosb, sinb, HH,   CC,  totq);
        rope_kernel<<<(totk + 255) / 256, 256>>>(k, cosb, sinb, HKVV, KVC, totk);
    }

    // Attention
    static bool attr_set = false;
    if (!attr_set) {
        cudaFuncSetAttribute(attn_kernel,
                             cudaFuncAttributeMaxDynamicSharedMemorySize,
                             ATT_SMEM_BYTES);
        attr_set = true;
    }
    attn_kernel<<<dim3(TT / BQ, BB * HH), 256, ATT_SMEM_BYTES>>>(q, k, v, gate, y);

    // Output projection (smooth path -> single tf32)
    tgemm_kernel<1><<<dim3(CC / 128, MROWS / 128), 256>>>(MROWS, CC, CC, y, Wo, out);
}

// round 10
// speedup vs baseline: 2.4156x; 1.2637x over previous
#include <cuda_runtime.h>
#include <cuda_bf16.h>
#include <cstdint>
#include <stdint.h>
#include <math.h>

// Problem constants
constexpr int BB  = 2;
constexpr int TT  = 2048;
constexpr int CC  = 2048;
constexpr int HH  = 16;
constexpr int HKVV = 4;
constexpr int DD  = 128;
constexpr int RR  = 64;
constexpr int KVC = HKVV * DD;      // 512
constexpr int REP = HH / HKVV;      // 4
constexpr int MROWS = BB * TT;      // 4096

// ---------------------------------------------------------------------------
// Scratch (static __device__ arrays; no allocations allowed)
// ---------------------------------------------------------------------------
__device__ float g_q[(size_t)MROWS * CC];            // 33.5 MB
__device__ float g_k[(size_t)MROWS * KVC];           //  8.4 MB
__device__ float g_v[(size_t)MROWS * KVC];           //  8.4 MB
__device__ float g_y[(size_t)MROWS * CC];            // 33.5 MB
__device__ float g_s[(size_t)BB * HH * TT * TT];     // 537 MB — e = exp(s - mn_kt) stash

// ---------------------------------------------------------------------------
// precision helpers
// ---------------------------------------------------------------------------
__device__ __forceinline__ unsigned int f2tf(float f) {
    unsigned int r;
    asm("cvt.rna.tf32.f32 %0, %1;" : "=r"(r) : "f"(f));
    return r;
}

// bf16x2 split of a float pair: hi = bf16(f), lo = bf16(f - hi), packed (f0 low, f1 high)
__device__ __forceinline__ void split_bf16x2(float f0, float f1,
                                             unsigned int& hi, unsigned int& lo) {
    __nv_bfloat162 h = __floats2bfloat162_rn(f0, f1);
    float2 hf = __bfloat1622float2(h);
    __nv_bfloat162 l = __floats2bfloat162_rn(f0 - hf.x, f1 - hf.y);
    hi = *reinterpret_cast<unsigned int*>(&h);
    lo = *reinterpret_cast<unsigned int*>(&l);
}

__device__ __forceinline__ void cp16(void* smem_ptr, const void* gptr) {
    unsigned int s = (unsigned int)__cvta_generic_to_shared(smem_ptr);
    asm volatile("cp.async.cg.shared.global [%0], [%1], 16;" :: "r"(s), "l"(gptr));
}

__device__ __forceinline__ void mma_tf32(float* d, const unsigned int* a, const unsigned int* b) {
    asm volatile(
        "mma.sync.aligned.m16n8k8.row.col.f32.tf32.tf32.f32 "
        "{%0,%1,%2,%3}, {%4,%5,%6,%7}, {%8,%9}, {%0,%1,%2,%3};"
        : "+f"(d[0]), "+f"(d[1]), "+f"(d[2]), "+f"(d[3])
        : "r"(a[0]), "r"(a[1]), "r"(a[2]), "r"(a[3]), "r"(b[0]), "r"(b[1]));
}

__device__ __forceinline__ void mma_bf16(float* d, const unsigned int* a, const unsigned int* b) {
    asm volatile(
        "mma.sync.aligned.m16n8k16.row.col.f32.bf16.bf16.f32 "
        "{%0,%1,%2,%3}, {%4,%5,%6,%7}, {%8,%9}, {%0,%1,%2,%3};"
        : "+f"(d[0]), "+f"(d[1]), "+f"(d[2]), "+f"(d[3])
        : "r"(a[0]), "r"(a[1]), "r"(a[2]), "r"(a[3]), "r"(b[0]), "r"(b[1]));
}

// ---------------------------------------------------------------------------
// Tensor-core GEMM, templated on PREC (3 = bf16x2 3-term, 1 = single tf32).
// Block tile 128x128x16, 8 warps (2x4), warp tile 64x32.
// ---------------------------------------------------------------------------
template <int PREC>
__global__ __launch_bounds__(256) void tgemm_kernel(
    int M, int N, int K,
    const float* __restrict__ A, const float* __restrict__ B,
    float* __restrict__ C)
{
    constexpr int BM = 128, BN = 128, BK = 16, AP = 20, BP = 136;
    __shared__ float As[2][BM * AP];
    __shared__ float Bs[2][BK * BP];

    const int tid  = threadIdx.x;
    const int lane = tid & 31;
    const int w    = tid >> 5;
    const int wm   = w >> 2;
    const int wn   = w & 3;
    const int grp  = lane >> 2;
    const int qid  = lane & 3;

    const size_t bm = (size_t)blockIdx.y * BM;
    const size_t bn = (size_t)blockIdx.x * BN;

    float acc[4][4][4];
    #pragma unroll
    for (int i = 0; i < 4; ++i)
        #pragma unroll
        for (int j = 0; j < 4; ++j)
            #pragma unroll
            for (int c = 0; c < 4; ++c) acc[i][j][c] = 0.0f;

    auto load_stage = [&](int k0, int buf) {
        #pragma unroll
        for (int c = 0; c < 2; ++c) {
            int idx = tid + c * 256;
            int row = idx >> 2, col = (idx & 3) * 4;
            cp16(&As[buf][row * AP + col], &A[(bm + row) * (size_t)K + k0 + col]);
        }
        #pragma unroll
        for (int c = 0; c < 2; ++c) {
            int idx = tid + c * 256;
            int row = idx >> 5, col = (idx & 31) * 4;
            cp16(&Bs[buf][row * BP + col], &B[(size_t)(k0 + row) * N + bn + col]);
        }
    };

    load_stage(0, 0);
    asm volatile("cp.async.commit_group;");

    const int nst = K / BK;
    for (int s = 0; s < nst; ++s) {
        asm volatile("cp.async.wait_group 0;");
        __syncthreads();
        const int cur = s & 1;
        if (s + 1 < nst) {
            load_stage((s + 1) * BK, cur ^ 1);
            asm volatile("cp.async.commit_group;");
        }

        const float* Asb = As[cur];
        const float* Bsb = Bs[cur];

        if (PREC == 3) {
            unsigned int ah[4][4], al[4][4], bh[4][2], bl[4][2];
            #pragma unroll
            for (int mt = 0; mt < 4; ++mt) {
                int r0 = wm * 64 + mt * 16 + grp;
                int c0 = 2 * qid;
                split_bf16x2(Asb[r0 * AP + c0],           Asb[r0 * AP + c0 + 1],
                             ah[mt][0], al[mt][0]);
                split_bf16x2(Asb[(r0 + 8) * AP + c0],     Asb[(r0 + 8) * AP + c0 + 1],
                             ah[mt][1], al[mt][1]);
                split_bf16x2(Asb[r0 * AP + c0 + 8],       Asb[r0 * AP + c0 + 9],
                             ah[mt][2], al[mt][2]);
                split_bf16x2(Asb[(r0 + 8) * AP + c0 + 8], Asb[(r0 + 8) * AP + c0 + 9],
                             ah[mt][3], al[mt][3]);
            }
            #pragma unroll
            for (int nt = 0; nt < 4; ++nt) {
                int c0 = wn * 32 + nt * 8 + grp;
                int k0 = 2 * qid;
                split_bf16x2(Bsb[k0 * BP + c0],       Bsb[(k0 + 1) * BP + c0],
                             bh[nt][0], bl[nt][0]);
                split_bf16x2(Bsb[(k0 + 8) * BP + c0], Bsb[(k0 + 9) * BP + c0],
                             bh[nt][1], bl[nt][1]);
            }
            #pragma unroll
            for (int mt = 0; mt < 4; ++mt)
                #pragma unroll
                for (int nt = 0; nt < 4; ++nt) {
                    mma_bf16(acc[mt][nt], al[mt], bh[nt]);
                    mma_bf16(acc[mt][nt], ah[mt], bl[nt]);
                    mma_bf16(acc[mt][nt], ah[mt], bh[nt]);
                }
        } else {
            #pragma unroll
            for (int ks = 0; ks < BK; ks += 8) {
                unsigned int af[4][4], bf[4][2];
                #pragma unroll
                for (int mt = 0; mt < 4; ++mt) {
                    int r0 = wm * 64 + mt * 16 + grp;
                    af[mt][0] = f2tf(Asb[r0 * AP + ks + qid]);
                    af[mt][1] = f2tf(Asb[(r0 + 8) * AP + ks + qid]);
                    af[mt][2] = f2tf(Asb[r0 * AP + ks + qid + 4]);
                    af[mt][3] = f2tf(Asb[(r0 + 8) * AP + ks + qid + 4]);
                }
                #pragma unroll
                for (int nt = 0; nt < 4; ++nt) {
                    int c0 = wn * 32 + nt * 8 + grp;
                    bf[nt][0] = f2tf(Bsb[(ks + qid) * BP + c0]);
                    bf[nt][1] = f2tf(Bsb[(ks + qid + 4) * BP + c0]);
                }
                #pragma unroll
                for (int mt = 0; mt < 4; ++mt)
                    #pragma unroll
                    for (int nt = 0; nt < 4; ++nt)
                        mma_tf32(acc[mt][nt], af[mt], bf[nt]);
            }
        }
        __syncthreads();
    }

    #pragma unroll
    for (int mt = 0; mt < 4; ++mt) {
        #pragma unroll
        for (int nt = 0; nt < 4; ++nt) {
            size_t r  = bm + wm * 64 + mt * 16 + grp;
            size_t c0 = bn + wn * 32 + nt * 8 + 2 * qid;
            *(float2*)&C[r * (size_t)N + c0]       = make_float2(acc[mt][nt][0], acc[mt][nt][1]);
            *(float2*)&C[(r + 8) * (size_t)N + c0] = make_float2(acc[mt][nt][2], acc[mt][nt][3]);
        }
    }
}

// ---------------------------------------------------------------------------
// RoPE (in place)
// ---------------------------------------------------------------------------
__global__ void rope_kernel(float* __restrict__ buf,
                            const float* __restrict__ cosb,
                            const float* __restrict__ sinb,
                            int nh, int pitch, int total)
{
    int idx = blockIdx.x * blockDim.x + threadIdx.x;
    if (idx >= total) return;
    constexpr int RH = RR / 2;
    int r   = idx % RH;
    int h   = (idx / RH) % nh;
    int row = idx / (RH * nh);
    int t   = row % TT;

    float* p = buf + (size_t)row * pitch + h * DD;
    float c1 = cosb[t * RR + r],       s1 = sinb[t * RR + r];
    float c2 = cosb[t * RR + r + RH],  s2 = sinb[t * RR + r + RH];
    float x1 = p[r], x2 = p[r + RH];
    p[r]      = x1 * c1 - x2 * s1;
    p[r + RH] = x2 * c2 + x1 * s2;
}

// ---------------------------------------------------------------------------
// Two-pass causal attention with threshold gating.
// Pass 1: QK via bf16x2 3-term MMA (Q/K split to bf16 hi/lo in smem),
//         S -> smem tile, stash e=exp(s-mn_kt) + mn_kt; online m,l.
// Pass 2: p = e * corr(r,kt), gate, PV via tf32 MMA.
// ---------------------------------------------------------------------------
constexpr int BQ  = 64;
constexpr int BKT = 64;
constexpr int KP  = 68;    // uint pitch for Qh/Ql/Kh/Kl (64 k-pairs + pad)
constexpr int SP  = 65;    // S tile float pitch
constexpr int VPITCH = 136;
constexpr int PPITCH = 68;
constexpr int RDP = 17;
constexpr int NKT = TT / BKT;
constexpr int ATT_SMEM_FLOATS =
    4 * BQ * KP + BQ * SP + BQ * VPITCH + BQ * PPITCH + BQ * RDP + NKT * BQ + 4 * BQ;
constexpr int ATT_SMEM_BYTES = ATT_SMEM_FLOATS * 4;   // 152064

__global__ __launch_bounds__(256, 1) void attn_kernel(
    const float* __restrict__ Q, const float* __restrict__ Km,
    const float* __restrict__ Vm, const float* __restrict__ gate,
    float* __restrict__ Y)
{
    extern __shared__ float sm[];
    unsigned int* Qhu = (unsigned int*)sm;          // [64][68]
    unsigned int* Qlu = Qhu + BQ * KP;              // [64][68]
    unsigned int* Khu = Qlu + BQ * KP;              // [64][68]
    unsigned int* Klu = Khu + BQ * KP;              // [64][68]
    float* Ss     = (float*)(Klu + BQ * KP);        // [64][65]
    float* Vs     = Ss + BQ * SP;                   // [64][136] tf32 bits
    float* Ps     = Vs + BQ * VPITCH;               // [64][68]  tf32 bits
    float* red    = Ps + BQ * PPITCH;               // [64][17]
    float* mn_all = red + BQ * RDP;                 // [32][64]
    float* m_s    = mn_all + NKT * BQ;              // [64]
    float* l_s    = m_s + BQ;
    float* mn_s   = l_s + BQ;                       // corr_s in pass 2
    float* li_s   = mn_s + BQ;
    unsigned int* Vsu = (unsigned int*)Vs;
    unsigned int* Psu = (unsigned int*)Ps;

    const int qt = blockIdx.x;
    const int bh = blockIdx.y;
    const int b  = bh / HH;
    const int h  = bh % HH;
    const int q0 = qt * BQ;
    const int tid  = threadIdx.x;
    const int ty   = tid / 16;
    const int tx   = tid % 16;
    const int lane = tid & 31;
    const int w    = tid >> 5;
    const int wm   = w >> 2;            // 0..1
    const int wn   = w & 3;             // 0..3
    const int grp  = lane >> 2;         // 0..7
    const int qid  = lane & 3;          // 0..3

    const float scale = 0.08838834764831845f;
    const float thr = 1.0f / (1.0f + __expf(-gate[h]));

    const float* Qb = Q  + (size_t)(b * TT) * CC  + h * DD;
    const float* Kb = Km + (size_t)(b * TT) * KVC + (h / REP) * DD;
    const float* Vb = Vm + (size_t)(b * TT) * KVC + (h / REP) * DD;
    float* Eb = g_s + ((size_t)bh * TT + q0) * TT;

    // Q tile -> bf16 hi/lo pairs (once)
    for (int e = tid; e < BQ * 64; e += 256) {
        int r = e >> 6, cp = e & 63;
        const float* src = &Qb[(size_t)(q0 + r) * CC + 2 * cp];
        unsigned int hi, lo;
        split_bf16x2(src[0], src[1], hi, lo);
        Qhu[r * KP + cp] = hi;
        Qlu[r * KP + cp] = lo;
    }
    if (tid < BQ) { m_s[tid] = -1e30f; l_s[tid] = 0.0f; }
    __syncthreads();

    const int m0  = wm * 32;
    const int n0q = wn * 16;

    // ---------------- PASS 1: QK via bf16x2 MMA, stash e + mn ----------------
    for (int kt = 0; kt <= qt; ++kt) {
        const int s0 = kt * BKT;

        // K tile -> bf16 hi/lo pairs
        for (int e = tid; e < BKT * 64; e += 256) {
            int r = e >> 6, cp = e & 63;
            const float* src = &Kb[(size_t)(s0 + r) * KVC + 2 * cp];
            unsigned int hi, lo;
            split_bf16x2(src[0], src[1], hi, lo);
            Khu[r * KP + cp] = hi;
            Klu[r * KP + cp] = lo;
        }
        __syncthreads();

        // S = Q K^T : 8 warps, warp tile 32m x 16n, 8 ksteps of k16
        float sacc[2][2][4];
        #pragma unroll
        for (int mt = 0; mt < 2; ++mt)
            #pragma unroll
            for (int nt = 0; nt < 2; ++nt)
                #pragma unroll
                for (int c = 0; c < 4; ++c) sacc[mt][nt][c] = 0.0f;

        #pragma unroll
        for (int ks = 0; ks < 8; ++ks) {
            const int kp0 = ks * 8;
            unsigned int ah[2][4], al[2][4], bh[2][2], bl[2][2];
            #pragma unroll
            for (int mt = 0; mt < 2; ++mt) {
                int rr = m0 + mt * 16 + grp;
                ah[mt][0] = Qhu[rr * KP + kp0 + qid];
                ah[mt][1] = Qhu[(rr + 8) * KP + kp0 + qid];
                ah[mt][2] = Qhu[rr * KP + kp0 + qid + 4];
                ah[mt][3] = Qhu[(rr + 8) * KP + kp0 + qid + 4];
                al[mt][0] = Qlu[rr * KP + kp0 + qid];
                al[mt][1] = Qlu[(rr + 8) * KP + kp0 + qid];
                al[mt][2] = Qlu[rr * KP + kp0 + qid + 4];
                al[mt][3] = Qlu[(rr + 8) * KP + kp0 + qid + 4];
            }
            #pragma unroll
            for (int nt = 0; nt < 2; ++nt) {
                int cc = n0q + nt * 8 + grp;
                bh[nt][0] = Khu[cc * KP + kp0 + qid];
                bh[nt][1] = Khu[cc * KP + kp0 + qid + 4];
                bl[nt][0] = Klu[cc * KP + kp0 + qid];
                bl[nt][1] = Klu[cc * KP + kp0 + qid + 4];
            }
            #pragma unroll
            for (int mt = 0; mt < 2; ++mt)
                #pragma unroll
                for (int nt = 0; nt < 2; ++nt) {
                    mma_bf16(sacc[mt][nt], al[mt], bh[nt]);
                    mma_bf16(sacc[mt][nt], ah[mt], bl[nt]);
                    mma_bf16(sacc[mt][nt], ah[mt], bh[nt]);
                }
        }

        // write scaled+masked S to smem tile
        const bool diag = (kt == qt);
        #pragma unroll
        for (int mt = 0; mt < 2; ++mt) {
            #pragma unroll
            for (int nt = 0; nt < 2; ++nt) {
                int rr = m0 + mt * 16 + grp;
                int cc = n0q + nt * 8 + 2 * qid;
                float v0 = sacc[mt][nt][0] * scale;
                float v1 = sacc[mt][nt][1] * scale;
                float v2 = sacc[mt][nt][2] * scale;
                float v3 = sacc[mt][nt][3] * scale;
                if (diag) {
                    if (cc > rr)         v0 = -1e30f;
                    if (cc + 1 > rr)     v1 = -1e30f;
                    if (cc > rr + 8)     v2 = -1e30f;
                    if (cc + 1 > rr + 8) v3 = -1e30f;
                }
                Ss[rr * SP + cc]           = v0;
                Ss[rr * SP + cc + 1]       = v1;
                Ss[(rr + 8) * SP + cc]     = v2;
                Ss[(rr + 8) * SP + cc + 1] = v3;
            }
        }
        __syncthreads();

        // row maxima
        #pragma unroll
        for (int i = 0; i < 4; ++i) {
            const int r = ty + 16 * i;
            float pm = -1e30f;
            #pragma unroll
            for (int j = 0; j < 4; ++j)
                pm = fmaxf(pm, Ss[r * SP + tx + 16 * j]);
            red[r * RDP + tx] = pm;
        }
        __syncthreads();

        float mo = 0.0f, mn = 0.0f;
        if (tid < BQ) {
            float tm = red[tid * RDP];
            #pragma unroll
            for (int k = 1; k < 16; ++k) tm = fmaxf(tm, red[tid * RDP + k]);
            mo = m_s[tid];
            mn = fmaxf(mo, tm);
            mn_s[tid] = mn;
            mn_all[kt * BQ + tid] = mn;
        }
        __syncthreads();

        // e = exp(s - mn_kt): stash + partial row sums
        #pragma unroll
        for (int i = 0; i < 4; ++i) {
            const int r = ty + 16 * i;
            const float mr = mn_s[r];
            float ps = 0.0f;
            #pragma unroll
            for (int j = 0; j < 4; ++j) {
                const int c = tx + 16 * j;
                float ei = __expf(Ss[r * SP + c] - mr);
                Eb[(size_t)r * TT + s0 + c] = ei;
                ps += ei;
            }
            red[r * RDP + tx] = ps;
        }
        __syncthreads();

        if (tid < BQ) {
            float ts = 0.0f;
            #pragma unroll
            for (int k = 0; k < 16; ++k) ts += red[tid * RDP + k];
            l_s[tid] = l_s[tid] * __expf(mo - mn) + ts;
            m_s[tid] = mn;
        }
        __syncthreads();
    }

    if (tid < BQ) li_s[tid] = 1.0f / l_s[tid];
    __syncthreads();

    // ---------------- PASS 2: gate + PV via tf32 MMA ----------------
    float o[2][4][4];
    #pragma unroll
    for (int mt = 0; mt < 2; ++mt)
        #pragma unroll
        for (int nt = 0; nt < 4; ++nt)
            #pragma unroll
            for (int c = 0; c < 4; ++c) o[mt][nt][c] = 0.0f;

    const int n0 = wn * 32;

    for (int kt = 0; kt <= qt; ++kt) {
        const int s0 = kt * BKT;

        for (int e = tid; e < BKT * DD; e += 256) {
            int r = e >> 7, d = e & 127;
            Vsu[r * VPITCH + d] = f2tf(Vb[(size_t)(s0 + r) * KVC + d]);
        }
        if (tid < BQ)
            mn_s[tid] = __expf(mn_all[kt * BQ + tid] - m_s[tid]) * li_s[tid];
        __syncthreads();

        for (int e = tid; e < BQ * BKT; e += 256) {
            int r = e >> 6, c = e & 63;
            float p = Eb[(size_t)r * TT + s0 + c] * mn_s[r];
            if (p < thr) p = 0.0f;
            Psu[r * PPITCH + c] = f2tf(p);
        }
        __syncthreads();

        #pragma unroll
        for (int k = 0; k < BKT; k += 8) {
            unsigned int af[2][4], bf[4][2];
            #pragma unroll
            for (int mt = 0; mt < 2; ++mt) {
                int rr = m0 + mt * 16 + grp;
                af[mt][0] = Psu[rr * PPITCH + k + qid];
                af[mt][1] = Psu[(rr + 8) * PPITCH + k + qid];
                af[mt][2] = Psu[rr * PPITCH + k + qid + 4];
                af[mt][3] = Psu[(rr + 8) * PPITCH + k + qid + 4];
            }
            #pragma unroll
            for (int nt = 0; nt < 4; ++nt) {
                int cc = n0 + nt * 8 + grp;
                bf[nt][0] = Vsu[(k + qid) * VPITCH + cc];
                bf[nt][1] = Vsu[(k + qid + 4) * VPITCH + cc];
            }
            #pragma unroll
            for (int mt = 0; mt < 2; ++mt)
                #pragma unroll
                for (int nt = 0; nt < 4; ++nt)
                    mma_tf32(o[mt][nt], af[mt], bf[nt]);
        }
        __syncthreads();
    }

    #pragma unroll
    for (int mt = 0; mt < 2; ++mt) {
        #pragma unroll
        for (int nt = 0; nt < 4; ++nt) {
            size_t row = (size_t)(b * TT + q0 + m0 + mt * 16 + grp);
            size_t col = h * DD + n0 + nt * 8 + 2 * qid;
            *(float2*)&Y[row * CC + col]       = make_float2(o[mt][nt][0], o[mt][nt][1]);
            *(float2*)&Y[(row + 8) * CC + col] = make_float2(o[mt][nt][2], o[mt][nt][3]);
        }
    }
}

// ---------------------------------------------------------------------------
// Launch
// ---------------------------------------------------------------------------
extern "C" void kernel_launch(void* const* d_in, const int* in_sizes, int n_in,
                              void* d_out, int out_size)
{
    const float* x    = (const float*)d_in[0];
    const float* cosb = (const float*)d_in[1];
    const float* sinb = (const float*)d_in[2];
    const float* Wq   = (const float*)d_in[3];
    const float* Wk   = (const float*)d_in[4];
    const float* Wv   = (const float*)d_in[5];
    const float* Wo   = (const float*)d_in[6];
    const float* gate = (const float*)d_in[7];
    float* out = (float*)d_out;

    float *q, *k, *v, *y;
    cudaGetSymbolAddress((void**)&q, g_q);
    cudaGetSymbolAddress((void**)&k, g_k);
    cudaGetSymbolAddress((void**)&v, g_v);
    cudaGetSymbolAddress((void**)&y, g_y);

    // Projections: q/k gate-critical -> bf16x2 3-term; v smooth -> single tf32
    tgemm_kernel<3><<<dim3(CC / 128, MROWS / 128), 256>>>(MROWS, CC,  CC, x, Wq, q);
    tgemm_kernel<3><<<dim3(KVC / 128, MROWS / 128), 256>>>(MROWS, KVC, CC, x, Wk, k);
    tgemm_kernel<1><<<dim3(KVC / 128, MROWS / 128), 256>>>(MROWS, KVC, CC, x, Wv, v);

    // RoPE (in place)
    {
        int totq = BB * TT * HH   * (RR / 2);
        int totk = BB * TT * HKVV * (RR / 2);
        rope_kernel<<<(totq + 255) / 256, 256>>>(q, cosb, sinb, HH,   CC,  totq);
        rope_kernel<<<(totk + 255) / 256, 256>>>(k, cosb, sinb, HKVV, KVC, totk);
    }

    // Attention
    static bool attr_set = false;
    if (!attr_set) {
        cudaFuncSetAttribute(attn_kernel,
                             cudaFuncAttributeMaxDynamicSharedMemorySize,
                             ATT_SMEM_BYTES);
        attr_set = true;
    }
    attn_kernel<<<dim3(TT / BQ, BB * HH), 256, ATT_SMEM_BYTES>>>(q, k, v, gate, y);

    // Output projection (smooth path -> single tf32)
    tgemm_kernel<1><<<dim3(CC / 128, MROWS / 128), 256>>>(MROWS, CC, CC, y, Wo, out);
}

// round 11
// speedup vs baseline: 3.1229x; 1.2928x over previous
#include <cuda_runtime.h>
#include <cuda_bf16.h>
#include <cstdint>
#include <stdint.h>
#include <math.h>

// Problem constants
constexpr int BB  = 2;
constexpr int TT  = 2048;
constexpr int CC  = 2048;
constexpr int HH  = 16;
constexpr int HKVV = 4;
constexpr int DD  = 128;
constexpr int RR  = 64;
constexpr int KVC = HKVV * DD;      // 512
constexpr int REP = HH / HKVV;      // 4
constexpr int MROWS = BB * TT;      // 4096

// ---------------------------------------------------------------------------
// Scratch (static __device__ arrays; no allocations allowed)
// ---------------------------------------------------------------------------
__device__ float g_q[(size_t)MROWS * CC];            // 33.5 MB (pre-rope q)
__device__ float g_k[(size_t)MROWS * KVC];           //  8.4 MB (pre-rope k)
__device__ float g_v[(size_t)MROWS * KVC];           //  8.4 MB
__device__ float g_y[(size_t)MROWS * CC];            // 33.5 MB
__device__ float g_s[(size_t)BB * HH * TT * TT];     // 537 MB — e stash
__device__ unsigned int g_qh[(size_t)MROWS * CC / 2];   // 16.8 MB — roped q, bf16 hi pairs
__device__ unsigned int g_ql[(size_t)MROWS * CC / 2];   // 16.8 MB — lo pairs
__device__ unsigned int g_kh[(size_t)MROWS * KVC / 2];  //  4.2 MB
__device__ unsigned int g_kl[(size_t)MROWS * KVC / 2];  //  4.2 MB

// ---------------------------------------------------------------------------
// precision helpers
// ---------------------------------------------------------------------------
__device__ __forceinline__ unsigned int f2tf(float f) {
    unsigned int r;
    asm("cvt.rna.tf32.f32 %0, %1;" : "=r"(r) : "f"(f));
    return r;
}

__device__ __forceinline__ void split_bf16x2(float f0, float f1,
                                             unsigned int& hi, unsigned int& lo) {
    __nv_bfloat162 h = __floats2bfloat162_rn(f0, f1);
    float2 hf = __bfloat1622float2(h);
    __nv_bfloat162 l = __floats2bfloat162_rn(f0 - hf.x, f1 - hf.y);
    hi = *reinterpret_cast<unsigned int*>(&h);
    lo = *reinterpret_cast<unsigned int*>(&l);
}

__device__ __forceinline__ void cp16(void* smem_ptr, const void* gptr) {
    unsigned int s = (unsigned int)__cvta_generic_to_shared(smem_ptr);
    asm volatile("cp.async.cg.shared.global [%0], [%1], 16;" :: "r"(s), "l"(gptr));
}

__device__ __forceinline__ void mma_tf32(float* d, const unsigned int* a, const unsigned int* b) {
    asm volatile(
        "mma.sync.aligned.m16n8k8.row.col.f32.tf32.tf32.f32 "
        "{%0,%1,%2,%3}, {%4,%5,%6,%7}, {%8,%9}, {%0,%1,%2,%3};"
        : "+f"(d[0]), "+f"(d[1]), "+f"(d[2]), "+f"(d[3])
        : "r"(a[0]), "r"(a[1]), "r"(a[2]), "r"(a[3]), "r"(b[0]), "r"(b[1]));
}

__device__ __forceinline__ void mma_bf16(float* d, const unsigned int* a, const unsigned int* b) {
    asm volatile(
        "mma.sync.aligned.m16n8k16.row.col.f32.bf16.bf16.f32 "
        "{%0,%1,%2,%3}, {%4,%5,%6,%7}, {%8,%9}, {%0,%1,%2,%3};"
        : "+f"(d[0]), "+f"(d[1]), "+f"(d[2]), "+f"(d[3])
        : "r"(a[0]), "r"(a[1]), "r"(a[2]), "r"(a[3]), "r"(b[0]), "r"(b[1]));
}

// ---------------------------------------------------------------------------
// Tensor-core GEMM, templated on PREC (3 = bf16x2 3-term, 1 = single tf32).
// (unchanged from R10)
// ---------------------------------------------------------------------------
template <int PREC>
__global__ __launch_bounds__(256) void tgemm_kernel(
    int M, int N, int K,
    const float* __restrict__ A, const float* __restrict__ B,
    float* __restrict__ C)
{
    constexpr int BM = 128, BN = 128, BK = 16, AP = 20, BP = 136;
    __shared__ float As[2][BM * AP];
    __shared__ float Bs[2][BK * BP];

    const int tid  = threadIdx.x;
    const int lane = tid & 31;
    const int w    = tid >> 5;
    const int wm   = w >> 2;
    const int wn   = w & 3;
    const int grp  = lane >> 2;
    const int qid  = lane & 3;

    const size_t bm = (size_t)blockIdx.y * BM;
    const size_t bn = (size_t)blockIdx.x * BN;

    float acc[4][4][4];
    #pragma unroll
    for (int i = 0; i < 4; ++i)
        #pragma unroll
        for (int j = 0; j < 4; ++j)
            #pragma unroll
            for (int c = 0; c < 4; ++c) acc[i][j][c] = 0.0f;

    auto load_stage = [&](int k0, int buf) {
        #pragma unroll
        for (int c = 0; c < 2; ++c) {
            int idx = tid + c * 256;
            int row = idx >> 2, col = (idx & 3) * 4;
            cp16(&As[buf][row * AP + col], &A[(bm + row) * (size_t)K + k0 + col]);
        }
        #pragma unroll
        for (int c = 0; c < 2; ++c) {
            int idx = tid + c * 256;
            int row = idx >> 5, col = (idx & 31) * 4;
            cp16(&Bs[buf][row * BP + col], &B[(size_t)(k0 + row) * N + bn + col]);
        }
    };

    load_stage(0, 0);
    asm volatile("cp.async.commit_group;");

    const int nst = K / BK;
    for (int s = 0; s < nst; ++s) {
        asm volatile("cp.async.wait_group 0;");
        __syncthreads();
        const int cur = s & 1;
        if (s + 1 < nst) {
            load_stage((s + 1) * BK, cur ^ 1);
            asm volatile("cp.async.commit_group;");
        }

        const float* Asb = As[cur];
        const float* Bsb = Bs[cur];

        if (PREC == 3) {
            unsigned int ah[4][4], al[4][4], bh[4][2], bl[4][2];
            #pragma unroll
            for (int mt = 0; mt < 4; ++mt) {
                int r0 = wm * 64 + mt * 16 + grp;
                int c0 = 2 * qid;
                split_bf16x2(Asb[r0 * AP + c0],           Asb[r0 * AP + c0 + 1],
                             ah[mt][0], al[mt][0]);
                split_bf16x2(Asb[(r0 + 8) * AP + c0],     Asb[(r0 + 8) * AP + c0 + 1],
                             ah[mt][1], al[mt][1]);
                split_bf16x2(Asb[r0 * AP + c0 + 8],       Asb[r0 * AP + c0 + 9],
                             ah[mt][2], al[mt][2]);
                split_bf16x2(Asb[(r0 + 8) * AP + c0 + 8], Asb[(r0 + 8) * AP + c0 + 9],
                             ah[mt][3], al[mt][3]);
            }
            #pragma unroll
            for (int nt = 0; nt < 4; ++nt) {
                int c0 = wn * 32 + nt * 8 + grp;
                int k0 = 2 * qid;
                split_bf16x2(Bsb[k0 * BP + c0],       Bsb[(k0 + 1) * BP + c0],
                             bh[nt][0], bl[nt][0]);
                split_bf16x2(Bsb[(k0 + 8) * BP + c0], Bsb[(k0 + 9) * BP + c0],
                             bh[nt][1], bl[nt][1]);
            }
            #pragma unroll
            for (int mt = 0; mt < 4; ++mt)
                #pragma unroll
                for (int nt = 0; nt < 4; ++nt) {
                    mma_bf16(acc[mt][nt], al[mt], bh[nt]);
                    mma_bf16(acc[mt][nt], ah[mt], bl[nt]);
                    mma_bf16(acc[mt][nt], ah[mt], bh[nt]);
                }
        } else {
            #pragma unroll
            for (int ks = 0; ks < BK; ks += 8) {
                unsigned int af[4][4], bf[4][2];
                #pragma unroll
                for (int mt = 0; mt < 4; ++mt) {
                    int r0 = wm * 64 + mt * 16 + grp;
                    af[mt][0] = f2tf(Asb[r0 * AP + ks + qid]);
                    af[mt][1] = f2tf(Asb[(r0 + 8) * AP + ks + qid]);
                    af[mt][2] = f2tf(Asb[r0 * AP + ks + qid + 4]);
                    af[mt][3] = f2tf(Asb[(r0 + 8) * AP + ks + qid + 4]);
                }
                #pragma unroll
                for (int nt = 0; nt < 4; ++nt) {
                    int c0 = wn * 32 + nt * 8 + grp;
                    bf[nt][0] = f2tf(Bsb[(ks + qid) * BP + c0]);
                    bf[nt][1] = f2tf(Bsb[(ks + qid + 4) * BP + c0]);
                }
                #pragma unroll
                for (int mt = 0; mt < 4; ++mt)
                    #pragma unroll
                    for (int nt = 0; nt < 4; ++nt)
                        mma_tf32(acc[mt][nt], af[mt], bf[nt]);
            }
        }
        __syncthreads();
    }

    #pragma unroll
    for (int mt = 0; mt < 4; ++mt) {
        #pragma unroll
        for (int nt = 0; nt < 4; ++nt) {
            size_t r  = bm + wm * 64 + mt * 16 + grp;
            size_t c0 = bn + wn * 32 + nt * 8 + 2 * qid;
            *(float2*)&C[r * (size_t)N + c0]       = make_float2(acc[mt][nt][0], acc[mt][nt][1]);
            *(float2*)&C[(r + 8) * (size_t)N + c0] = make_float2(acc[mt][nt][2], acc[mt][nt][3]);
        }
    }
}

// ---------------------------------------------------------------------------
// Fused RoPE + bf16 hi/lo split+pack: src fp32 (heads of 128 dims, first 64
// roped with rotate-half RH=32) -> packed uint pair arrays.
// One thread per value-pair.
// ---------------------------------------------------------------------------
__global__ void rope_split_kernel(const float* __restrict__ src,
                                  unsigned int* __restrict__ dsth,
                                  unsigned int* __restrict__ dstl,
                                  const float* __restrict__ cosb,
                                  const float* __restrict__ sinb,
                                  int nh, int pitch, int total)
{
    int idx = blockIdx.x * blockDim.x + threadIdx.x;
    if (idx >= total) return;
    int cp  = idx & 63;
    int h   = (idx >> 6) % nh;
    int row = idx / (64 * nh);
    int t   = row % TT;

    const float* p = src + (size_t)row * pitch + h * DD;

    float f[2];
    #pragma unroll
    for (int i = 0; i < 2; ++i) {
        int d = 2 * cp + i;
        float x = p[d];
        if (d < 32)
            f[i] = x * cosb[t * RR + d] - p[d + 32] * sinb[t * RR + d];
        else if (d < 64)
            f[i] = x * cosb[t * RR + d] + p[d - 32] * sinb[t * RR + d];
        else
            f[i] = x;
    }
    unsigned int hi, lo;
    split_bf16x2(f[0], f[1], hi, lo);
    size_t o = (size_t)row * (pitch / 2) + h * 64 + cp;
    dsth[o] = hi;
    dstl[o] = lo;
}

// ---------------------------------------------------------------------------
// Two-pass causal attention with threshold gating.
// Pass 1: QK via bf16x2 3-term MMA from pre-split packed q/k; stash
//         e=exp(s-mn_kt), running max mn_kt, and tile max tmax_kt; online m,l.
// Pass 2: exact tile-skip (max row prob < thr), else p=e*corr, gate, PV tf32 MMA.
// ---------------------------------------------------------------------------
constexpr int BQ  = 64;
constexpr int BKT = 64;
constexpr int KP  = 68;
constexpr int SP  = 65;
constexpr int VPITCH = 136;
constexpr int PPITCH = 68;
constexpr int RDP = 17;
constexpr int NKT = TT / BKT;
constexpr int ATT_SMEM_FLOATS =
    4 * BQ * KP + BQ * SP + BQ * VPITCH + BQ * PPITCH + BQ * RDP
    + 2 * NKT * BQ + 4 * BQ + 4;
constexpr int ATT_SMEM_BYTES = ATT_SMEM_FLOATS * 4;   // 160272

__global__ __launch_bounds__(256, 1) void attn_kernel(
    const float* __restrict__ Vm, const float* __restrict__ gate,
    float* __restrict__ Y)
{
    extern __shared__ float sm[];
    unsigned int* Qhu = (unsigned int*)sm;          // [64][68]
    unsigned int* Qlu = Qhu + BQ * KP;
    unsigned int* Khu = Qlu + BQ * KP;
    unsigned int* Klu = Khu + BQ * KP;
    float* Ss       = (float*)(Klu + BQ * KP);      // [64][65]
    float* Vs       = Ss + BQ * SP;                 // [64][136] tf32 bits
    float* Ps       = Vs + BQ * VPITCH;             // [64][68]  tf32 bits
    float* red      = Ps + BQ * PPITCH;             // [64][17]
    float* mn_all   = red + BQ * RDP;               // [32][64] running max at kt
    float* tmax_all = mn_all + NKT * BQ;            // [32][64] raw tile max
    float* m_s      = tmax_all + NKT * BQ;          // [64]
    float* l_s      = m_s + BQ;
    float* mn_s     = l_s + BQ;                     // corr in pass 2
    float* li_s     = mn_s + BQ;
    float* sflag    = li_s + BQ;                    // [4]
    unsigned int* Vsu = (unsigned int*)Vs;
    unsigned int* Psu = (unsigned int*)Ps;

    const int qt = blockIdx.x;
    const int bh = blockIdx.y;
    const int b  = bh / HH;
    const int h  = bh % HH;
    const int q0 = qt * BQ;
    const int tid  = threadIdx.x;
    const int ty   = tid / 16;
    const int tx   = tid % 16;
    const int lane = tid & 31;
    const int w    = tid >> 5;
    const int wm   = w >> 2;
    const int wn   = w & 3;
    const int grp  = lane >> 2;
    const int qid  = lane & 3;

    const float scale = 0.08838834764831845f;
    const float thr = 1.0f / (1.0f + __expf(-gate[h]));

    const unsigned int* Qhg = g_qh + (size_t)(b * TT) * (CC / 2) + h * 64;
    const unsigned int* Qlg = g_ql + (size_t)(b * TT) * (CC / 2) + h * 64;
    const unsigned int* Khg = g_kh + (size_t)(b * TT) * (KVC / 2) + (h / REP) * 64;
    const unsigned int* Klg = g_kl + (size_t)(b * TT) * (KVC / 2) + (h / REP) * 64;
    const float* Vb = Vm + (size_t)(b * TT) * KVC + (h / REP) * DD;
    float* Eb = g_s + ((size_t)bh * TT + q0) * TT;

    // Q tile (pre-split, packed)
    for (int e = tid; e < BQ * 64; e += 256) {
        int r = e >> 6, cp = e & 63;
        Qhu[r * KP + cp] = Qhg[(size_t)(q0 + r) * (CC / 2) + cp];
        Qlu[r * KP + cp] = Qlg[(size_t)(q0 + r) * (CC / 2) + cp];
    }
    if (tid < BQ) { m_s[tid] = -1e30f; l_s[tid] = 0.0f; }
    __syncthreads();

    const int m0  = wm * 32;
    const int n0q = wn * 16;

    // ---------------- PASS 1 ----------------
    for (int kt = 0; kt <= qt; ++kt) {
        const int s0 = kt * BKT;

        for (int e = tid; e < BKT * 64; e += 256) {
            int r = e >> 6, cp = e & 63;
            Khu[r * KP + cp] = Khg[(size_t)(s0 + r) * (KVC / 2) + cp];
            Klu[r * KP + cp] = Klg[(size_t)(s0 + r) * (KVC / 2) + cp];
        }
        __syncthreads();

        float sacc[2][2][4];
        #pragma unroll
        for (int mt = 0; mt < 2; ++mt)
            #pragma unroll
            for (int nt = 0; nt < 2; ++nt)
                #pragma unroll
                for (int c = 0; c < 4; ++c) sacc[mt][nt][c] = 0.0f;

        #pragma unroll
        for (int ks = 0; ks < 8; ++ks) {
            const int kp0 = ks * 8;
            unsigned int ah[2][4], al[2][4], bh[2][2], bl[2][2];
            #pragma unroll
            for (int mt = 0; mt < 2; ++mt) {
                int rr = m0 + mt * 16 + grp;
                ah[mt][0] = Qhu[rr * KP + kp0 + qid];
                ah[mt][1] = Qhu[(rr + 8) * KP + kp0 + qid];
                ah[mt][2] = Qhu[rr * KP + kp0 + qid + 4];
                ah[mt][3] = Qhu[(rr + 8) * KP + kp0 + qid + 4];
                al[mt][0] = Qlu[rr * KP + kp0 + qid];
                al[mt][1] = Qlu[(rr + 8) * KP + kp0 + qid];
                al[mt][2] = Qlu[rr * KP + kp0 + qid + 4];
                al[mt][3] = Qlu[(rr + 8) * KP + kp0 + qid + 4];
            }
            #pragma unroll
            for (int nt = 0; nt < 2; ++nt) {
                int cc = n0q + nt * 8 + grp;
                bh[nt][0] = Khu[cc * KP + kp0 + qid];
                bh[nt][1] = Khu[cc * KP + kp0 + qid + 4];
                bl[nt][0] = Klu[cc * KP + kp0 + qid];
                bl[nt][1] = Klu[cc * KP + kp0 + qid + 4];
            }
            #pragma unroll
            for (int mt = 0; mt < 2; ++mt)
                #pragma unroll
                for (int nt = 0; nt < 2; ++nt) {
                    mma_bf16(sacc[mt][nt], al[mt], bh[nt]);
                    mma_bf16(sacc[mt][nt], ah[mt], bl[nt]);
                    mma_bf16(sacc[mt][nt], ah[mt], bh[nt]);
                }
        }

        const bool diag = (kt == qt);
        #pragma unroll
        for (int mt = 0; mt < 2; ++mt) {
            #pragma unroll
            for (int nt = 0; nt < 2; ++nt) {
                int rr = m0 + mt * 16 + grp;
                int cc = n0q + nt * 8 + 2 * qid;
                float v0 = sacc[mt][nt][0] * scale;
                float v1 = sacc[mt][nt][1] * scale;
                float v2 = sacc[mt][nt][2] * scale;
                float v3 = sacc[mt][nt][3] * scale;
                if (diag) {
                    if (cc > rr)         v0 = -1e30f;
                    if (cc + 1 > rr)     v1 = -1e30f;
                    if (cc > rr + 8)     v2 = -1e30f;
                    if (cc + 1 > rr + 8) v3 = -1e30f;
                }
                Ss[rr * SP + cc]           = v0;
                Ss[rr * SP + cc + 1]       = v1;
                Ss[(rr + 8) * SP + cc]     = v2;
                Ss[(rr + 8) * SP + cc + 1] = v3;
            }
        }
        __syncthreads();

        #pragma unroll
        for (int i = 0; i < 4; ++i) {
            const int r = ty + 16 * i;
            float pm = -1e30f;
            #pragma unroll
            for (int j = 0; j < 4; ++j)
                pm = fmaxf(pm, Ss[r * SP + tx + 16 * j]);
            red[r * RDP + tx] = pm;
        }
        __syncthreads();

        float mo = 0.0f, mn = 0.0f;
        if (tid < BQ) {
            float tm = red[tid * RDP];
            #pragma unroll
            for (int k = 1; k < 16; ++k) tm = fmaxf(tm, red[tid * RDP + k]);
            mo = m_s[tid];
            mn = fmaxf(mo, tm);
            mn_s[tid] = mn;
            mn_all[kt * BQ + tid] = mn;
            tmax_all[kt * BQ + tid] = tm;
        }
        __syncthreads();

        #pragma unroll
        for (int i = 0; i < 4; ++i) {
            const int r = ty + 16 * i;
            const float mr = mn_s[r];
            float ps = 0.0f;
            #pragma unroll
            for (int j = 0; j < 4; ++j) {
                const int c = tx + 16 * j;
                float ei = __expf(Ss[r * SP + c] - mr);
                Eb[(size_t)r * TT + s0 + c] = ei;
                ps += ei;
            }
            red[r * RDP + tx] = ps;
        }
        __syncthreads();

        if (tid < BQ) {
            float ts = 0.0f;
            #pragma unroll
            for (int k = 0; k < 16; ++k) ts += red[tid * RDP + k];
            l_s[tid] = l_s[tid] * __expf(mo - mn) + ts;
            m_s[tid] = mn;
        }
        __syncthreads();
    }

    if (tid < BQ) li_s[tid] = 1.0f / l_s[tid];
    __syncthreads();

    // ---------------- PASS 2: tile-skip + gate + PV ----------------
    float o[2][4][4];
    #pragma unroll
    for (int mt = 0; mt < 2; ++mt)
        #pragma unroll
        for (int nt = 0; nt < 4; ++nt)
            #pragma unroll
            for (int c = 0; c < 4; ++c) o[mt][nt][c] = 0.0f;

    const int n0 = wn * 32;

    for (int kt = 0; kt <= qt; ++kt) {
        const int s0 = kt * BKT;

        // exact per-tile survival test (slack makes skipping conservative)
        if (tid == 0) sflag[0] = 0.0f;
        __syncthreads();
        if (tid < BQ) {
            float pmax = __expf(tmax_all[kt * BQ + tid] - m_s[tid]) * li_s[tid];
            mn_s[tid] = __expf(mn_all[kt * BQ + tid] - m_s[tid]) * li_s[tid];
            if (pmax * 1.00001f >= thr) sflag[0] = 1.0f;
        }
        __syncthreads();
        if (sflag[0] == 0.0f) continue;    // whole tile gated to zero — skip

        for (int e = tid; e < BKT * DD; e += 256) {
            int r = e >> 7, d = e & 127;
            Vsu[r * VPITCH + d] = f2tf(Vb[(size_t)(s0 + r) * KVC + d]);
        }
        __syncthreads();

        for (int e = tid; e < BQ * BKT; e += 256) {
            int r = e >> 6, c = e & 63;
            float p = Eb[(size_t)r * TT + s0 + c] * mn_s[r];
            if (p < thr) p = 0.0f;
            Psu[r * PPITCH + c] = f2tf(p);
        }
        __syncthreads();

        #pragma unroll
        for (int k = 0; k < BKT; k += 8) {
            unsigned int af[2][4], bf[4][2];
            #pragma unroll
            for (int mt = 0; mt < 2; ++mt) {
                int rr = m0 + mt * 16 + grp;
                af[mt][0] = Psu[rr * PPITCH + k + qid];
                af[mt][1] = Psu[(rr + 8) * PPITCH + k + qid];
                af[mt][2] = Psu[rr * PPITCH + k + qid + 4];
                af[mt][3] = Psu[(rr + 8) * PPITCH + k + qid + 4];
            }
            #pragma unroll
            for (int nt = 0; nt < 4; ++nt) {
                int cc = n0 + nt * 8 + grp;
                bf[nt][0] = Vsu[(k + qid) * VPITCH + cc];
                bf[nt][1] = Vsu[(k + qid + 4) * VPITCH + cc];
            }
            #pragma unroll
            for (int mt = 0; mt < 2; ++mt)
                #pragma unroll
                for (int nt = 0; nt < 4; ++nt)
                    mma_tf32(o[mt][nt], af[mt], bf[nt]);
        }
        __syncthreads();
    }

    #pragma unroll
    for (int mt = 0; mt < 2; ++mt) {
        #pragma unroll
        for (int nt = 0; nt < 4; ++nt) {
            size_t row = (size_t)(b * TT + q0 + m0 + mt * 16 + grp);
            size_t col = h * DD + n0 + nt * 8 + 2 * qid;
            *(float2*)&Y[row * CC + col]       = make_float2(o[mt][nt][0], o[mt][nt][1]);
            *(float2*)&Y[(row + 8) * CC + col] = make_float2(o[mt][nt][2], o[mt][nt][3]);
        }
    }
}

// ---------------------------------------------------------------------------
// Launch
// ---------------------------------------------------------------------------
extern "C" void kernel_launch(void* const* d_in, const int* in_sizes, int n_in,
                              void* d_out, int out_size)
{
    const float* x    = (const float*)d_in[0];
    const float* cosb = (const float*)d_in[1];
    const float* sinb = (const float*)d_in[2];
    const float* Wq   = (const float*)d_in[3];
    const float* Wk   = (const float*)d_in[4];
    const float* Wv   = (const float*)d_in[5];
    const float* Wo   = (const float*)d_in[6];
    const float* gate = (const float*)d_in[7];
    float* out = (float*)d_out;

    float *q, *k, *v, *y;
    unsigned int *qh, *ql, *kh, *kl;
    cudaGetSymbolAddress((void**)&q,  g_q);
    cudaGetSymbolAddress((void**)&k,  g_k);
    cudaGetSymbolAddress((void**)&v,  g_v);
    cudaGetSymbolAddress((void**)&y,  g_y);
    cudaGetSymbolAddress((void**)&qh, g_qh);
    cudaGetSymbolAddress((void**)&ql, g_ql);
    cudaGetSymbolAddress((void**)&kh, g_kh);
    cudaGetSymbolAddress((void**)&kl, g_kl);

    // Projections
    tgemm_kernel<3><<<dim3(CC / 128, MROWS / 128), 256>>>(MROWS, CC,  CC, x, Wq, q);
    tgemm_kernel<3><<<dim3(KVC / 128, MROWS / 128), 256>>>(MROWS, KVC, CC, x, Wk, k);
    tgemm_kernel<1><<<dim3(KVC / 128, MROWS / 128), 256>>>(MROWS, KVC, CC, x, Wv, v);

    // Fused RoPE + bf16 hi/lo split+pack for q and k
    {
        int totq = MROWS * HH * 64;
        int totk = MROWS * HKVV * 64;
        rope_split_kernel<<<(totq + 255) / 256, 256>>>(q, qh, ql, cosb, sinb, HH, CC, totq);
        rope_split_kernel<<<(totk + 255) / 256, 256>>>(k, kh, kl, cosb, sinb, HKVV, KVC, totk);
    }

    // Attention
    static bool attr_set = false;
    if (!attr_set) {
        cudaFuncSetAttribute(attn_kernel,
                             cudaFuncAttributeMaxDynamicSharedMemorySize,
                             ATT_SMEM_BYTES);
        attr_set = true;
    }
    attn_kernel<<<dim3(TT / BQ, BB * HH), 256, ATT_SMEM_BYTES>>>(v, gate, y);

    // Output projection
    tgemm_kernel<1><<<dim3(CC / 128, MROWS / 128), 256>>>(MROWS, CC, CC, y, Wo, out);
}